// round 13
// baseline (speedup 1.0000x reference)
#include <cuda_runtime.h>
#include <cuda_bf16.h>
#include <math.h>
#include <cstdint>

#define H     300
#define G     900
#define NB    1024
#define LSEQ  64
#define NTHREADS 320
#define NNODES 49152

// ---- input GEMM config ----
#define KP  960
#define NP  1024
#define MT  128
#define NKB2 (KP / 32)
#define SROW 80
#define GSTG 20480
#define GSM_TOT (3 * GSTG)

// ---- recurrent mma config ----
#define GP    304                  // rows per gate (19 m16 tiles)
#define RROWS 912                  // 3*GP, 57 m16 tiles
#define RMT   57
#define RKC   38                   // 19 hi + 19 lo k16 chunks
#define HSS   648                  // h-split row stride (bf16)
#define HFS   304
#define RBT   16                   // graphs per CTA
#define RNT   512                  // 16 warps
#define PWIT  10                   // ceil(RBT*H / RNT)

// dynamic smem layout (bytes) — no weight ring anymore
#define SM_D    0
#define SM_HS   (RROWS * 16 * 4)              // 58368
#define SM_HF   (SM_HS + RBT * HSS * 2)       // 79104
#define SM_BH   (SM_HF + RBT * HFS * 4)       // 98560
#define SM_BI   (SM_BH + 3600)                // 102160
#define SM_MISC (SM_BI + 3600)                // 105760
#define SM_TOT  (SM_MISC + 128)               // 105888

__device__ __forceinline__ float sigm(float x) { return 1.f / (1.f + __expf(-x)); }
__device__ __forceinline__ float tanh_fast(float x) {
    float s = 1.f / (1.f + __expf(-2.f * x));
    return 2.f * s - 1.f;
}
__device__ __forceinline__ uint32_t smem_u32(const void* p) {
    uint32_t a;
    asm("{ .reg .u64 t; cvta.to.shared.u64 t, %1; cvt.u32.u64 %0, t; }" : "=r"(a) : "l"(p));
    return a;
}
__device__ __forceinline__ float ldcs(const float* p) {
    float v; asm volatile("ld.global.cs.f32 %0, [%1];" : "=f"(v) : "l"(p)); return v;
}
__device__ __forceinline__ void stcs(float* p, float v) {
    asm volatile("st.global.cs.f32 [%0], %1;" :: "l"(p), "f"(v));
}

// ---------------- device scratch ----------------
__device__ __align__(16) __nv_bfloat16 g_abf[(size_t)NNODES * KP];
__device__ __align__(16) __nv_bfloat16 g_bbf[2][(size_t)NP * KP];
// W_hh in fragment order: [dir][kc][tile][lane] -> 16B (4 u32 A-frag regs)
__device__ __align__(16) uint4 g_wfr[(size_t)2 * RKC * RMT * 32];
__device__ float g_xg[2][(size_t)NNODES * G];
__device__ float g_h0[NB * H];
__device__ int   g_sstart[NB];
__device__ int   g_slen[NB];

// ---------------- 1) merged prep: seg | convA | convB | convW(frag) ----------------
__global__ void __launch_bounds__(256) k_prep(const float* __restrict__ node,
                                              const float* __restrict__ bias,
                                              const int* __restrict__ batch,
                                              const int* __restrict__ pos,
                                              const float* __restrict__ wif,
                                              const float* __restrict__ wib,
                                              const float* __restrict__ whf,
                                              const float* __restrict__ whb,
                                              int n) {
    __shared__ float sb[H];
    const int bx = blockIdx.x, tid = threadIdx.x;
    if (bx < 64) {
        for (int i = bx * 256 + tid; i < n; i += 64 * 256) {
            int b = batch[i];
            if (pos[i] == 0) g_sstart[b] = i;
            if (i == n - 1 || batch[i + 1] != b) g_slen[b] = pos[i] + 1;
        }
    } else if (bx < 64 + n) {
        int i = bx - 64;
        for (int k = tid; k < H; k += 256) {
            float v = node[(size_t)i * H + k] + bias[k];
            sb[k] = v > 0.f ? v : 0.f;
        }
        __syncthreads();
        __nv_bfloat16* dst = g_abf + (size_t)i * KP;
        for (int kp = tid; kp < KP; kp += 256) {
            __nv_bfloat16 o = __float2bfloat16(0.f);
            int k = -1; bool lo = false;
            if (kp < 300)                    { k = kp; }
            else if (kp >= 320 && kp < 620)  { k = kp - 320; lo = true; }
            else if (kp >= 640 && kp < 940)  { k = kp - 640; }
            if (k >= 0) {
                float m = sb[k];
                __nv_bfloat16 hi = __float2bfloat16(m);
                o = lo ? __float2bfloat16(m - __bfloat162float(hi)) : hi;
            }
            dst[kp] = o;
        }
    } else if (bx < 64 + n + 512) {
        size_t tot = (size_t)2 * NP * KP;
        int bb = bx - 64 - n;
        for (size_t idx = (size_t)bb * 256 + tid; idx < tot; idx += (size_t)512 * 256) {
            int dir = (int)(idx / ((size_t)NP * KP));
            size_t r = idx - (size_t)dir * NP * KP;
            int g = (int)(r / KP), kp = (int)(r - (size_t)g * KP);
            __nv_bfloat16 o = __float2bfloat16(0.f);
            int k = -1; bool lo = false;
            if (kp < 300)                    { k = kp; }
            else if (kp >= 320 && kp < 620)  { k = kp - 320; }
            else if (kp >= 640 && kp < 940)  { k = kp - 640; lo = true; }
            if (k >= 0 && g < G) {
                const float* w = dir ? wib : wif;
                float v = w[(size_t)g * H + k];
                __nv_bfloat16 hi = __float2bfloat16(v);
                o = lo ? __float2bfloat16(v - __bfloat162float(hi)) : hi;
            }
            g_bbf[dir][r] = o;
        }
    } else {
        // ---- convW: fragment-order layout, one u32 (2 bf16) per element ----
        const int tot = 2 * RKC * RMT * 32 * 4;          // u32 count
        uint32_t* wout = (uint32_t*)g_wfr;
        int bb = bx - 64 - n - 512;
        for (int idx = bb * 256 + tid; idx < tot; idx += 256 * 256) {
            int e  = idx & 3;
            int r1 = idx >> 2;
            int l  = r1 & 31;
            int r2 = r1 >> 5;
            int mt = r2 % RMT;
            int r3 = r2 / RMT;
            int kc = r3 % RKC;
            int dir = r3 / RKC;
            int row = mt * 16 + (l >> 2) + (e & 1) * 8;   // gate-space row
            int col = (l & 3) * 2 + ((e >> 1) & 1) * 8;   // within-chunk k (pair base)
            int gate = row / GP, j = row % GP;
            bool lo = kc >= 19;
            int k0 = (lo ? kc - 19 : kc) * 16 + col;
            const float* w = dir ? whb : whf;
            uint32_t o = 0;
#pragma unroll
            for (int q = 0; q < 2; ++q) {
                int k = k0 + q;
                __nv_bfloat16 bv = __float2bfloat16(0.f);
                if (j < H && k < H) {
                    float v = w[(size_t)(gate * H + j) * H + k];
                    __nv_bfloat16 hi = __float2bfloat16(v);
                    bv = lo ? __float2bfloat16(v - __bfloat162float(hi)) : hi;
                }
                unsigned short us = *(unsigned short*)&bv;
                o |= (uint32_t)us << (16 * q);
            }
            wout[idx] = o;
        }
    }
}

// ---------------- 2) h0 = per-graph segment max ----------------
__global__ void __launch_bounds__(NTHREADS) k_h0(const float* __restrict__ node) {
    int b = blockIdx.x, h = threadIdx.x;
    if (h >= H) return;
    int s = g_sstart[b], l = g_slen[b];
    float m = -3.402823466e38f;
    for (int i = 0; i < l; ++i) m = fmaxf(m, node[(size_t)(s + i) * H + h]);
    g_h0[b * H + h] = m;
}

// ---------------- 3) input GEMM (proven round-8) ----------------
__global__ void __launch_bounds__(256, 2) k_gemm_mma(const float* __restrict__ bih_f,
                                                     const float* __restrict__ bih_b) {
    extern __shared__ unsigned char gsm[];
    const int tid = threadIdx.x, lane = tid & 31, wid = tid >> 5;
    const int dir = blockIdx.x >> 3, ntile = blockIdx.x & 7;
    const int m0 = blockIdx.y * MT, n0 = ntile * 128;
    const int wm = wid & 3, wn = wid >> 2;

    const __nv_bfloat16* __restrict__ A = g_abf + (size_t)m0 * KP;
    const __nv_bfloat16* __restrict__ B = g_bbf[dir] + (size_t)n0 * KP;
    const uint32_t s0 = smem_u32(gsm);

    float d[2][8][4];
#pragma unroll
    for (int mi = 0; mi < 2; ++mi)
#pragma unroll
        for (int ni = 0; ni < 8; ++ni)
#pragma unroll
            for (int e = 0; e < 4; ++e) d[mi][ni][e] = 0.f;

#define ISSUE_STAGE(kb, stg) do {                                                   \
    _Pragma("unroll")                                                               \
    for (int _p = 0; _p < 2; ++_p) {                                                \
        int _u = _p * 256 + tid, _row = _u >> 2, _c = _u & 3;                       \
        const void* _ga = A + (size_t)_row * KP + (kb) * 32 + _c * 8;               \
        uint32_t _da = s0 + (stg) * GSTG + _row * SROW + _c * 16;                   \
        asm volatile("cp.async.cg.shared.global [%0], [%1], 16;" :: "r"(_da), "l"(_ga)); \
        const void* _gb = B + (size_t)_row * KP + (kb) * 32 + _c * 8;               \
        uint32_t _db = s0 + (stg) * GSTG + 10240 + _row * SROW + _c * 16;           \
        asm volatile("cp.async.cg.shared.global [%0], [%1], 16;" :: "r"(_db), "l"(_gb)); \
    }                                                                               \
    asm volatile("cp.async.commit_group;" ::: "memory");                            \
} while (0)

#define GEMM_COMPUTE(a32, b32, NIMAX)                                               \
    _Pragma("unroll")                                                               \
    for (int ks = 0; ks < 2; ++ks) {                                                \
        uint32_t af[2][4];                                                          \
        _Pragma("unroll")                                                           \
        for (int mi = 0; mi < 2; ++mi) {                                            \
            int r0 = wm * 32 + mi * 16 + (lane >> 2);                               \
            af[mi][0] = (a32)[r0 * 20 + ks * 8 + (lane & 3)];                       \
            af[mi][1] = (a32)[(r0 + 8) * 20 + ks * 8 + (lane & 3)];                 \
            af[mi][2] = (a32)[r0 * 20 + ks * 8 + 4 + (lane & 3)];                   \
            af[mi][3] = (a32)[(r0 + 8) * 20 + ks * 8 + 4 + (lane & 3)];             \
        }                                                                           \
        _Pragma("unroll")                                                           \
        for (int ni = 0; ni < (NIMAX); ++ni) {                                      \
            int cn = wn * 64 + ni * 8 + (lane >> 2);                                \
            uint32_t b0 = (b32)[cn * 20 + ks * 8 + (lane & 3)];                     \
            uint32_t b1 = (b32)[cn * 20 + ks * 8 + 4 + (lane & 3)];                 \
            _Pragma("unroll")                                                       \
            for (int mi = 0; mi < 2; ++mi) {                                        \
                asm volatile(                                                       \
                    "mma.sync.aligned.m16n8k16.row.col.f32.bf16.bf16.f32 "          \
                    "{%0,%1,%2,%3}, {%4,%5,%6,%7}, {%8,%9}, {%0,%1,%2,%3};"         \
                    : "+f"(d[mi][ni][0]), "+f"(d[mi][ni][1]),                       \
                      "+f"(d[mi][ni][2]), "+f"(d[mi][ni][3])                        \
                    : "r"(af[mi][0]), "r"(af[mi][1]), "r"(af[mi][2]), "r"(af[mi][3]), \
                      "r"(b0), "r"(b1));                                            \
            }                                                                       \
        }                                                                           \
    }

    ISSUE_STAGE(0, 0);
    ISSUE_STAGE(1, 1);
    const bool tail = (ntile == 7);
    int stg = 0;
    for (int kb = 0; kb < NKB2; ++kb) {
        if (kb <= NKB2 - 2) { asm volatile("cp.async.wait_group 1;" ::: "memory"); }
        else                { asm volatile("cp.async.wait_group 0;" ::: "memory"); }
        __syncthreads();
        const uint32_t* a32 = (const uint32_t*)(gsm + stg * GSTG);
        const uint32_t* b32 = (const uint32_t*)(gsm + stg * GSTG + 10240);
        if (!tail) { GEMM_COMPUTE(a32, b32, 8); }
        else       { GEMM_COMPUTE(a32, b32, 1); }
        if (kb + 2 < NKB2) {
            int ns = stg + 2; if (ns >= 3) ns -= 3;
            ISSUE_STAGE(kb + 2, ns);
        }
        if (++stg == 3) stg = 0;
    }
#undef ISSUE_STAGE
#undef GEMM_COMPUTE

    const float* __restrict__ bih = dir ? bih_b : bih_f;
    float* __restrict__ xg = g_xg[dir];
    const int nimax = tail ? 1 : 8;
#pragma unroll
    for (int mi = 0; mi < 2; ++mi) {
        int r0 = m0 + wm * 32 + mi * 16 + (lane >> 2);
        for (int ni = 0; ni < nimax; ++ni) {
            int g = n0 + wn * 64 + ni * 8 + (lane & 3) * 2;
            if (g < G) {
                float bg0 = bih[g], bg1 = bih[g + 1];
                *(float2*)(xg + (size_t)r0 * G + g) =
                    make_float2(d[mi][ni][0] + bg0, d[mi][ni][1] + bg1);
                *(float2*)(xg + (size_t)(r0 + 8) * G + g) =
                    make_float2(d[mi][ni][2] + bg0, d[mi][ni][3] + bg1);
            }
        }
    }
}

// ---------------- 4) recurrent GRU: direct-LDG fragment weights ----------------
__global__ void __launch_bounds__(RNT, 1) k_recur_mma(const float* __restrict__ bih_f,
                                                      const float* __restrict__ bih_b,
                                                      const float* __restrict__ bhh_f,
                                                      const float* __restrict__ bhh_b,
                                                      float* __restrict__ out) {
    extern __shared__ char smem[];
    float*           Dsm  = (float*)(smem + SM_D);
    uint32_t*        hs32 = (uint32_t*)(smem + SM_HS);
    __nv_bfloat16*   hsb  = (__nv_bfloat16*)(smem + SM_HS);
    float*           hf   = (float*)(smem + SM_HF);
    float*           sbhh = (float*)(smem + SM_BH);
    float*           sbih = (float*)(smem + SM_BI);
    int*             sst  = (int*)(smem + SM_MISC);
    int*             sln  = sst + RBT;

    const int tid = threadIdx.x, lane = tid & 31, wid = tid >> 5;
    const int dir = blockIdx.y;
    const int b0 = blockIdx.x * RBT;
    // uneven warp tiling: warps 0-8 own 4 m16 tiles, warps 9-15 own 3 (57 total)
    const int ntl   = (wid < 9) ? 4 : 3;
    const int mtw   = (wid < 9) ? wid * 4 : 36 + (wid - 9) * 3;
    const int wrow0 = mtw * 16;

    const uint4* __restrict__ wfr = g_wfr + (size_t)dir * RKC * RMT * 32;
    const float* __restrict__ xg = g_xg[dir];

    // direct global->register A-fragment load (ld.global.nc.v4)
#define LDG_AFR(dst, kc) do {                                                       \
    _Pragma("unroll")                                                               \
    for (int _i = 0; _i < 4; ++_i) {                                                \
        if (_i < ntl) {                                                             \
            const uint4* _p = wfr + ((size_t)(kc) * RMT + mtw + _i) * 32 + lane;    \
            asm volatile("ld.global.nc.v4.u32 {%0,%1,%2,%3}, [%4];"                 \
                : "=r"((dst)[_i][0]), "=r"((dst)[_i][1]),                           \
                  "=r"((dst)[_i][2]), "=r"((dst)[_i][3])                            \
                : "l"(_p));                                                         \
        }                                                                           \
    }                                                                               \
} while (0)

#define MMA_ACC(ac, Af, B0, B1)                                                     \
    asm volatile("mma.sync.aligned.m16n8k16.row.col.f32.bf16.bf16.f32 "             \
        "{%0,%1,%2,%3}, {%4,%5,%6,%7}, {%8,%9}, {%0,%1,%2,%3};"                     \
        : "+f"((ac)[0]), "+f"((ac)[1]), "+f"((ac)[2]), "+f"((ac)[3])                \
        : "r"((Af)[0]), "r"((Af)[1]), "r"((Af)[2]), "r"((Af)[3]), "r"(B0), "r"(B1))

    if (tid < RBT) { sst[tid] = g_sstart[b0 + tid]; sln[tid] = g_slen[b0 + tid]; }
    for (int i = tid; i < RBT * (HSS / 2); i += RNT) hs32[i] = 0u;
    {
        const float* bhh = dir ? bhh_b : bhh_f;
        const float* bih = dir ? bih_b : bih_f;
        for (int i = tid; i < G; i += RNT) { sbhh[i] = bhh[i]; sbih[i] = bih[i]; }
    }
    __syncthreads();
    for (int it = tid; it < RBT * H; it += RNT) {
        int j = it >> 4, b = it & 15;
        float v = g_h0[(b0 + b) * H + j];
        hf[b * HFS + j] = v;
        __nv_bfloat16 hi = __float2bfloat16(v);
        hsb[b * HSS + j] = hi;
        hsb[b * HSS + 320 + j] = __float2bfloat16(v - __bfloat162float(hi));
    }
    __syncthreads();

    for (int s = 0; s < LSEQ; ++s) {
        int t = dir ? (LSEQ - 1 - s) : s;

        // prefetch this step's xg slice into registers (hidden under MMA loop)
        float xp[PWIT][3];
#pragma unroll
        for (int ii = 0; ii < PWIT; ++ii) {
            int it = tid + ii * RNT;
            if (it < RBT * H) {
                int j = it >> 4, b = it & 15;
                if (t < sln[b]) {
                    const float* xr = xg + (size_t)(sst[b] + t) * G;
                    xp[ii][0] = ldcs(xr + j);
                    xp[ii][1] = ldcs(xr + H + j);
                    xp[ii][2] = ldcs(xr + 2 * H + j);
                } else {
                    xp[ii][0] = sbih[j];
                    xp[ii][1] = sbih[H + j];
                    xp[ii][2] = sbih[2 * H + j];
                }
            }
        }

        float acc[4][2][4];
#pragma unroll
        for (int i = 0; i < 4; ++i)
#pragma unroll
            for (int nt = 0; nt < 2; ++nt)
#pragma unroll
                for (int e = 0; e < 4; ++e) acc[i][nt][e] = 0.f;

        uint32_t Af[2][4][4];
        LDG_AFR(Af[0], 0);

        // ---- hi chunks 0..18: W_hi x (h_hi + h_lo) ----
#pragma unroll 1
        for (int kc = 0; kc < 19; ++kc) {
            LDG_AFR(Af[(kc + 1) & 1], kc + 1);      // prefetch next chunk's A
            const int hk = kc * 8;
            uint32_t bh[2][2], bl[2][2];
#pragma unroll
            for (int nt = 0; nt < 2; ++nt) {
                int rb = (nt * 8 + (lane >> 2)) * (HSS / 2);
                bh[nt][0] = hs32[rb + hk + (lane & 3)];
                bh[nt][1] = hs32[rb + hk + 4 + (lane & 3)];
                bl[nt][0] = hs32[rb + 160 + hk + (lane & 3)];
                bl[nt][1] = hs32[rb + 160 + hk + 4 + (lane & 3)];
            }
            for (int i = 0; i < ntl; ++i) {
#pragma unroll
                for (int nt = 0; nt < 2; ++nt)
                    MMA_ACC(acc[i][nt], Af[kc & 1][i], bh[nt][0], bh[nt][1]);
            }
            for (int i = 0; i < ntl; ++i) {
#pragma unroll
                for (int nt = 0; nt < 2; ++nt)
                    MMA_ACC(acc[i][nt], Af[kc & 1][i], bl[nt][0], bl[nt][1]);
            }
        }
        // ---- lo chunks 19..37: W_lo x h_hi ----
#pragma unroll 1
        for (int kc = 19; kc < RKC; ++kc) {
            if (kc + 1 < RKC) LDG_AFR(Af[(kc + 1) & 1], kc + 1);
            const int hk = (kc - 19) * 8;
            uint32_t bh[2][2];
#pragma unroll
            for (int nt = 0; nt < 2; ++nt) {
                int rb = (nt * 8 + (lane >> 2)) * (HSS / 2);
                bh[nt][0] = hs32[rb + hk + (lane & 3)];
                bh[nt][1] = hs32[rb + hk + 4 + (lane & 3)];
            }
            for (int i = 0; i < ntl; ++i) {
#pragma unroll
                for (int nt = 0; nt < 2; ++nt)
                    MMA_ACC(acc[i][nt], Af[kc & 1][i], bh[nt][0], bh[nt][1]);
            }
        }

        // write hg preactivations D[row][graph]
        for (int i = 0; i < ntl; ++i) {
            int r0 = wrow0 + i * 16 + (lane >> 2);
#pragma unroll
            for (int nt = 0; nt < 2; ++nt) {
                int c = nt * 8 + (lane & 3) * 2;
                *(float2*)(Dsm + r0 * 16 + c) = make_float2(acc[i][nt][0], acc[i][nt][1]);
                *(float2*)(Dsm + (r0 + 8) * 16 + c) = make_float2(acc[i][nt][2], acc[i][nt][3]);
            }
        }
        __syncthreads();

        // pointwise GRU update (xg already in registers)
#pragma unroll
        for (int ii = 0; ii < PWIT; ++ii) {
            int it = tid + ii * RNT;
            if (it < RBT * H) {
                int j = it >> 4, b = it & 15;
                bool valid = t < sln[b];
                float hgr = Dsm[j * 16 + b];
                float hgz = Dsm[(GP + j) * 16 + b];
                float hgn = Dsm[(2 * GP + j) * 16 + b];
                float r  = sigm(xp[ii][0] + hgr + sbhh[j]);
                float z  = sigm(xp[ii][1] + hgz + sbhh[H + j]);
                float nn = tanh_fast(xp[ii][2] + r * (hgn + sbhh[2 * H + j]));
                float hp = hf[b * HFS + j];
                float hv = (1.f - z) * nn + z * hp;
                hf[b * HFS + j] = hv;
                __nv_bfloat16 hi = __float2bfloat16(hv);
                hsb[b * HSS + j] = hi;
                hsb[b * HSS + 320 + j] = __float2bfloat16(hv - __bfloat162float(hi));
                if (valid)
                    stcs(out + (size_t)(sst[b] + t) * (2 * H) + dir * H + j, hv);
            }
        }
        __syncthreads();
    }
#undef LDG_AFR
#undef MMA_ACC
}

// ---------------- host entry ----------------
extern "C" void kernel_launch(void* const* d_in, const int* in_sizes, int n_in,
                              void* d_out, int out_size) {
    const float* node   = (const float*)d_in[0];
    const int*   batch  = (const int*)d_in[1];
    const int*   pos    = (const int*)d_in[2];
    const float* bias   = (const float*)d_in[3];
    const float* w_ih_f = (const float*)d_in[4];
    const float* w_hh_f = (const float*)d_in[5];
    const float* b_ih_f = (const float*)d_in[6];
    const float* b_hh_f = (const float*)d_in[7];
    const float* w_ih_b = (const float*)d_in[8];
    const float* w_hh_b = (const float*)d_in[9];
    const float* b_ih_b = (const float*)d_in[10];
    const float* b_hh_b = (const float*)d_in[11];
    float* out = (float*)d_out;
    int n = in_sizes[0] / H;

    cudaFuncSetAttribute(k_gemm_mma, cudaFuncAttributeMaxDynamicSharedMemorySize, GSM_TOT);
    cudaFuncSetAttribute(k_recur_mma, cudaFuncAttributeMaxDynamicSharedMemorySize, SM_TOT);

    int gprep = 64 + n + 512 + 256;
    k_prep<<<gprep, 256>>>(node, bias, batch, pos, w_ih_f, w_ih_b, w_hh_f, w_hh_b, n);
    k_h0<<<NB, NTHREADS>>>(node);
    k_gemm_mma<<<dim3(16, n / MT), 256, GSM_TOT>>>(b_ih_f, b_ih_b);
    k_recur_mma<<<dim3(NB / RBT, 2), RNT, SM_TOT>>>(b_ih_f, b_ih_b, b_hh_f, b_hh_b, out);
}

// round 14
// speedup vs baseline: 1.7100x; 1.7100x over previous
#include <cuda_runtime.h>
#include <cuda_bf16.h>
#include <math.h>
#include <cstdint>

#define H     300
#define G     900
#define NB    1024
#define LSEQ  64
#define NTHREADS 320
#define NNODES 49152

// ---- input GEMM config ----
#define KP  960
#define NP  1024
#define MT  128
#define NKB2 (KP / 32)
#define SROW 80
#define GSTG 20480
#define GSM_TOT (3 * GSTG)

// ---- recurrent mma config ----
#define GP    304                  // rows per gate (19 m16 tiles)
#define RROWS 912                  // 3*GP, 57 m16 tiles
#define RKC   38                   // 19 hi + 19 lo k16 chunks
#define WSTG  (RROWS * 32)         // ring stage: 29184 B
#define HSS   648                  // h-split row stride (bf16)
#define HFS   304
#define RBT   16                   // graphs per CTA
#define RNT   640                  // 20 warps: 19 compute + 1 xg producer
#define NCW   19                   // compute warps
#define XQP   4864                 // xq plane stride (16*304 floats)

// dynamic smem layout (bytes)
#define SM_W    0
#define SM_HS   (4 * WSTG)                    // 116736: h split (bf16)
#define SM_HF   (SM_HS + RBT * HSS * 2)       // 137472: h fp32
#define SM_XQ   (SM_HF + RBT * HFS * 4)       // 156928: xg stage (3*16*304 f32)
#define SM_BH   (SM_XQ + 3 * XQP * 4)         // 215296
#define SM_BI   (SM_BH + 3600)                // 218896
#define SM_MISC (SM_BI + 3600)                // 222496
#define SM_TOT  (SM_MISC + 128)               // 222624

__device__ __forceinline__ float sigm(float x) { return 1.f / (1.f + __expf(-x)); }
__device__ __forceinline__ float tanh_fast(float x) {
    float s = 1.f / (1.f + __expf(-2.f * x));
    return 2.f * s - 1.f;
}
__device__ __forceinline__ uint32_t smem_u32(const void* p) {
    uint32_t a;
    asm("{ .reg .u64 t; cvta.to.shared.u64 t, %1; cvt.u32.u64 %0, t; }" : "=r"(a) : "l"(p));
    return a;
}
__device__ __forceinline__ void stcs(float* p, float v) {
    asm volatile("st.global.cs.f32 [%0], %1;" :: "l"(p), "f"(v));
}

// ---------------- device scratch ----------------
__device__ __align__(16) __nv_bfloat16 g_abf[(size_t)NNODES * KP];
__device__ __align__(16) __nv_bfloat16 g_bbf[2][(size_t)NP * KP];
__device__ __align__(16) __nv_bfloat16 g_gwr[(size_t)2 * RKC * RROWS * 16];
__device__ float g_xg[2][(size_t)NNODES * G];
__device__ float g_h0[NB * H];
__device__ int   g_sstart[NB];
__device__ int   g_slen[NB];

// ---------------- 1) merged prep: seg | convA | convB | convW ----------------
__global__ void __launch_bounds__(256) k_prep(const float* __restrict__ node,
                                              const float* __restrict__ bias,
                                              const int* __restrict__ batch,
                                              const int* __restrict__ pos,
                                              const float* __restrict__ wif,
                                              const float* __restrict__ wib,
                                              const float* __restrict__ whf,
                                              const float* __restrict__ whb,
                                              int n) {
    __shared__ float sb[H];
    const int bx = blockIdx.x, tid = threadIdx.x;
    if (bx < 64) {
        for (int i = bx * 256 + tid; i < n; i += 64 * 256) {
            int b = batch[i];
            if (pos[i] == 0) g_sstart[b] = i;
            if (i == n - 1 || batch[i + 1] != b) g_slen[b] = pos[i] + 1;
        }
    } else if (bx < 64 + n) {
        int i = bx - 64;
        for (int k = tid; k < H; k += 256) {
            float v = node[(size_t)i * H + k] + bias[k];
            sb[k] = v > 0.f ? v : 0.f;
        }
        __syncthreads();
        __nv_bfloat16* dst = g_abf + (size_t)i * KP;
        for (int kp = tid; kp < KP; kp += 256) {
            __nv_bfloat16 o = __float2bfloat16(0.f);
            int k = -1; bool lo = false;
            if (kp < 300)                    { k = kp; }
            else if (kp >= 320 && kp < 620)  { k = kp - 320; lo = true; }
            else if (kp >= 640 && kp < 940)  { k = kp - 640; }
            if (k >= 0) {
                float m = sb[k];
                __nv_bfloat16 hi = __float2bfloat16(m);
                o = lo ? __float2bfloat16(m - __bfloat162float(hi)) : hi;
            }
            dst[kp] = o;
        }
    } else if (bx < 64 + n + 512) {
        size_t tot = (size_t)2 * NP * KP;
        int bb = bx - 64 - n;
        for (size_t idx = (size_t)bb * 256 + tid; idx < tot; idx += (size_t)512 * 256) {
            int dir = (int)(idx / ((size_t)NP * KP));
            size_t r = idx - (size_t)dir * NP * KP;
            int g = (int)(r / KP), kp = (int)(r - (size_t)g * KP);
            __nv_bfloat16 o = __float2bfloat16(0.f);
            int k = -1; bool lo = false;
            if (kp < 300)                    { k = kp; }
            else if (kp >= 320 && kp < 620)  { k = kp - 320; }
            else if (kp >= 640 && kp < 940)  { k = kp - 640; lo = true; }
            if (k >= 0 && g < G) {
                const float* w = dir ? wib : wif;
                float v = w[(size_t)g * H + k];
                __nv_bfloat16 hi = __float2bfloat16(v);
                o = lo ? __float2bfloat16(v - __bfloat162float(hi)) : hi;
            }
            g_bbf[dir][r] = o;
        }
    } else {
        const int tot = 2 * RKC * RROWS * 16;
        int bb = bx - 64 - n - 512;
        for (int idx = bb * 256 + tid; idx < tot; idx += 256 * 256) {
            int dir = idx / (RKC * RROWS * 16);
            int r = idx % (RKC * RROWS * 16);
            int kc = r / (RROWS * 16);
            int rr = r % (RROWS * 16);
            int row = rr >> 4, c = rr & 15;
            int gate = row / GP, j = row % GP;
            bool lo = kc >= 19;
            int k = (lo ? kc - 19 : kc) * 16 + c;
            __nv_bfloat16 o = __float2bfloat16(0.f);
            if (j < H && k < H) {
                const float* w = dir ? whb : whf;
                float v = w[(size_t)(gate * H + j) * H + k];
                __nv_bfloat16 hi = __float2bfloat16(v);
                o = lo ? __float2bfloat16(v - __bfloat162float(hi)) : hi;
            }
            g_gwr[idx] = o;
        }
    }
}

// ---------------- 2) h0 = per-graph segment max ----------------
__global__ void __launch_bounds__(NTHREADS) k_h0(const float* __restrict__ node) {
    int b = blockIdx.x, h = threadIdx.x;
    if (h >= H) return;
    int s = g_sstart[b], l = g_slen[b];
    float m = -3.402823466e38f;
    for (int i = 0; i < l; ++i) m = fmaxf(m, node[(size_t)(s + i) * H + h]);
    g_h0[b * H + h] = m;
}

// ---------------- 3) input GEMM (proven round-8) ----------------
__global__ void __launch_bounds__(256, 2) k_gemm_mma(const float* __restrict__ bih_f,
                                                     const float* __restrict__ bih_b) {
    extern __shared__ unsigned char gsm[];
    const int tid = threadIdx.x, lane = tid & 31, wid = tid >> 5;
    const int dir = blockIdx.x >> 3, ntile = blockIdx.x & 7;
    const int m0 = blockIdx.y * MT, n0 = ntile * 128;
    const int wm = wid & 3, wn = wid >> 2;

    const __nv_bfloat16* __restrict__ A = g_abf + (size_t)m0 * KP;
    const __nv_bfloat16* __restrict__ B = g_bbf[dir] + (size_t)n0 * KP;
    const uint32_t s0 = smem_u32(gsm);

    float d[2][8][4];
#pragma unroll
    for (int mi = 0; mi < 2; ++mi)
#pragma unroll
        for (int ni = 0; ni < 8; ++ni)
#pragma unroll
            for (int e = 0; e < 4; ++e) d[mi][ni][e] = 0.f;

#define ISSUE_STAGE(kb, stg) do {                                                   \
    _Pragma("unroll")                                                               \
    for (int _p = 0; _p < 2; ++_p) {                                                \
        int _u = _p * 256 + tid, _row = _u >> 2, _c = _u & 3;                       \
        const void* _ga = A + (size_t)_row * KP + (kb) * 32 + _c * 8;               \
        uint32_t _da = s0 + (stg) * GSTG + _row * SROW + _c * 16;                   \
        asm volatile("cp.async.cg.shared.global [%0], [%1], 16;" :: "r"(_da), "l"(_ga)); \
        const void* _gb = B + (size_t)_row * KP + (kb) * 32 + _c * 8;               \
        uint32_t _db = s0 + (stg) * GSTG + 10240 + _row * SROW + _c * 16;           \
        asm volatile("cp.async.cg.shared.global [%0], [%1], 16;" :: "r"(_db), "l"(_gb)); \
    }                                                                               \
    asm volatile("cp.async.commit_group;" ::: "memory");                            \
} while (0)

#define GEMM_COMPUTE(a32, b32, NIMAX)                                               \
    _Pragma("unroll")                                                               \
    for (int ks = 0; ks < 2; ++ks) {                                                \
        uint32_t af[2][4];                                                          \
        _Pragma("unroll")                                                           \
        for (int mi = 0; mi < 2; ++mi) {                                            \
            int r0 = wm * 32 + mi * 16 + (lane >> 2);                               \
            af[mi][0] = (a32)[r0 * 20 + ks * 8 + (lane & 3)];                       \
            af[mi][1] = (a32)[(r0 + 8) * 20 + ks * 8 + (lane & 3)];                 \
            af[mi][2] = (a32)[r0 * 20 + ks * 8 + 4 + (lane & 3)];                   \
            af[mi][3] = (a32)[(r0 + 8) * 20 + ks * 8 + 4 + (lane & 3)];             \
        }                                                                           \
        _Pragma("unroll")                                                           \
        for (int ni = 0; ni < (NIMAX); ++ni) {                                      \
            int cn = wn * 64 + ni * 8 + (lane >> 2);                                \
            uint32_t b0 = (b32)[cn * 20 + ks * 8 + (lane & 3)];                     \
            uint32_t b1 = (b32)[cn * 20 + ks * 8 + 4 + (lane & 3)];                 \
            _Pragma("unroll")                                                       \
            for (int mi = 0; mi < 2; ++mi) {                                        \
                asm volatile(                                                       \
                    "mma.sync.aligned.m16n8k16.row.col.f32.bf16.bf16.f32 "          \
                    "{%0,%1,%2,%3}, {%4,%5,%6,%7}, {%8,%9}, {%0,%1,%2,%3};"         \
                    : "+f"(d[mi][ni][0]), "+f"(d[mi][ni][1]),                       \
                      "+f"(d[mi][ni][2]), "+f"(d[mi][ni][3])                        \
                    : "r"(af[mi][0]), "r"(af[mi][1]), "r"(af[mi][2]), "r"(af[mi][3]), \
                      "r"(b0), "r"(b1));                                            \
            }                                                                       \
        }                                                                           \
    }

    ISSUE_STAGE(0, 0);
    ISSUE_STAGE(1, 1);
    const bool tail = (ntile == 7);
    int stg = 0;
    for (int kb = 0; kb < NKB2; ++kb) {
        if (kb <= NKB2 - 2) { asm volatile("cp.async.wait_group 1;" ::: "memory"); }
        else                { asm volatile("cp.async.wait_group 0;" ::: "memory"); }
        __syncthreads();
        const uint32_t* a32 = (const uint32_t*)(gsm + stg * GSTG);
        const uint32_t* b32 = (const uint32_t*)(gsm + stg * GSTG + 10240);
        if (!tail) { GEMM_COMPUTE(a32, b32, 8); }
        else       { GEMM_COMPUTE(a32, b32, 1); }
        if (kb + 2 < NKB2) {
            int ns = stg + 2; if (ns >= 3) ns -= 3;
            ISSUE_STAGE(kb + 2, ns);
        }
        if (++stg == 3) stg = 0;
    }
#undef ISSUE_STAGE
#undef GEMM_COMPUTE

    const float* __restrict__ bih = dir ? bih_b : bih_f;
    float* __restrict__ xg = g_xg[dir];
    const int nimax = tail ? 1 : 8;
#pragma unroll
    for (int mi = 0; mi < 2; ++mi) {
        int r0 = m0 + wm * 32 + mi * 16 + (lane >> 2);
        for (int ni = 0; ni < nimax; ++ni) {
            int g = n0 + wn * 64 + ni * 8 + (lane & 3) * 2;
            if (g < G) {
                float bg0 = bih[g], bg1 = bih[g + 1];
                *(float2*)(xg + (size_t)r0 * G + g) =
                    make_float2(d[mi][ni][0] + bg0, d[mi][ni][1] + bg1);
                *(float2*)(xg + (size_t)(r0 + 8) * G + g) =
                    make_float2(d[mi][ni][2] + bg0, d[mi][ni][3] + bg1);
            }
        }
    }
}

// ---------------- 4) recurrent GRU: gate-aligned warps, register pointwise ----------------
__global__ void __launch_bounds__(RNT, 1) k_recur_mma(const float* __restrict__ bih_f,
                                                      const float* __restrict__ bih_b,
                                                      const float* __restrict__ bhh_f,
                                                      const float* __restrict__ bhh_b,
                                                      float* __restrict__ out) {
    extern __shared__ char smem[];
    uint32_t*        hs32 = (uint32_t*)(smem + SM_HS);
    __nv_bfloat16*   hsb  = (__nv_bfloat16*)(smem + SM_HS);
    float*           hf   = (float*)(smem + SM_HF);
    float*           xq   = (float*)(smem + SM_XQ);
    float*           sbhh = (float*)(smem + SM_BH);
    float*           sbih = (float*)(smem + SM_BI);
    int*             sst  = (int*)(smem + SM_MISC);
    int*             sln  = sst + RBT;

    const int tid = threadIdx.x, lane = tid & 31, wid = tid >> 5;
    const int dir = blockIdx.y;
    const int b0 = blockIdx.x * RBT;
    const uint32_t swb = smem_u32(smem);
    const bool iscomp = (wid < NCW);

    // warp w owns tiles {w, w+19, w+38} = gates 0,1,2 of j-group w
    uint32_t afro[3];
    if (iscomp) {
        int lsel = lane >> 3, lrow = lane & 7;
        int half = lsel >> 1;
#pragma unroll
        for (int i = 0; i < 3; ++i) {
            int row = (wid + NCW * i) * 16 + lrow + ((lsel & 1) << 3);
            afro[i] = row * 32 + ((half ^ ((row >> 2) & 1)) << 4);
        }
    }

    const __nv_bfloat16* __restrict__ gw = g_gwr + (size_t)dir * RKC * RROWS * 16;
    const float* __restrict__ xg = g_xg[dir];

#define ISSUE_WCHUNK(pfc, stg) do {                                                 \
    const char* _src = (const char*)(gw + (size_t)(pfc) * (RROWS * 16));            \
    _Pragma("unroll")                                                               \
    for (int _i = 0; _i < 3; ++_i) {                                                \
        int _row = (wid + NCW * _i) * 16 + (lane >> 1);                             \
        int _half = lane & 1;                                                       \
        int _hsw = _half ^ ((_row >> 2) & 1);                                       \
        uint32_t _d = swb + (stg) * WSTG + _row * 32 + (_hsw << 4);                 \
        const void* _s = _src + _row * 32 + _half * 16;                             \
        asm volatile("cp.async.cg.shared.global [%0], [%1], 16;" :: "r"(_d), "l"(_s)); \
    }                                                                               \
    asm volatile("cp.async.commit_group;" ::: "memory");                            \
} while (0)

#define MMA_ACC(ac, Af, B0, B1)                                                     \
    asm volatile("mma.sync.aligned.m16n8k16.row.col.f32.bf16.bf16.f32 "             \
        "{%0,%1,%2,%3}, {%4,%5,%6,%7}, {%8,%9}, {%0,%1,%2,%3};"                     \
        : "+f"((ac)[0]), "+f"((ac)[1]), "+f"((ac)[2]), "+f"((ac)[3])                \
        : "r"((Af)[0]), "r"((Af)[1]), "r"((Af)[2]), "r"((Af)[3]), "r"(B0), "r"(B1))

    if (iscomp) {
#pragma unroll
        for (int p = 0; p < 4; ++p) ISSUE_WCHUNK(p, p);
    }

    if (tid < RBT) { sst[tid] = g_sstart[b0 + tid]; sln[tid] = g_slen[b0 + tid]; }
    for (int i = tid; i < RBT * (HSS / 2); i += RNT) hs32[i] = 0u;
    {
        const float* bhh = dir ? bhh_b : bhh_f;
        const float* bih = dir ? bih_b : bih_f;
        for (int i = tid; i < G; i += RNT) { sbhh[i] = bhh[i]; sbih[i] = bih[i]; }
    }
    __syncthreads();
    for (int it = tid; it < RBT * H; it += RNT) {
        int j = it >> 4, b = it & 15;
        float v = g_h0[(b0 + b) * H + j];
        hf[b * HFS + j] = v;
        __nv_bfloat16 hi = __float2bfloat16(v);
        hsb[b * HSS + j] = hi;
        hsb[b * HSS + 320 + j] = __float2bfloat16(v - __bfloat162float(hi));
    }
    __syncthreads();

    for (int s = 0; s < LSEQ; ++s) {
        int t = dir ? (LSEQ - 1 - s) : s;
        float acc[3][2][4];

        if (iscomp) {
#pragma unroll
            for (int g = 0; g < 3; ++g)
#pragma unroll
                for (int nt = 0; nt < 2; ++nt)
#pragma unroll
                    for (int e = 0; e < 4; ++e) acc[g][nt][e] = 0.f;

            const int sbase = 2 * (s & 1);      // (38*s) mod 4
            // ---- hi chunks 0..18: W_hi x (h_hi + h_lo) ----
#pragma unroll 1
            for (int kc = 0; kc < 19; ++kc) {
                const int stage = (kc + sbase) & 3;
                asm volatile("cp.async.wait_group 3;" ::: "memory");
                const uint32_t wbase = swb + (uint32_t)stage * WSTG;
                const int hk = kc * 8;
                uint32_t A[3][4];
#pragma unroll
                for (int i = 0; i < 3; ++i) {
                    asm volatile("ldmatrix.sync.aligned.m8n8.x4.shared.b16 "
                                 "{%0,%1,%2,%3}, [%4];"
                                 : "=r"(A[i][0]), "=r"(A[i][1]), "=r"(A[i][2]), "=r"(A[i][3])
                                 : "r"(wbase + afro[i]));
                }
                int pfc = kc + 4; if (pfc >= RKC) pfc -= RKC;
                ISSUE_WCHUNK(pfc, stage);
                uint32_t bh[2][2], bl[2][2];
#pragma unroll
                for (int nt = 0; nt < 2; ++nt) {
                    int rb = (nt * 8 + (lane >> 2)) * (HSS / 2);
                    bh[nt][0] = hs32[rb + hk + (lane & 3)];
                    bh[nt][1] = hs32[rb + hk + 4 + (lane & 3)];
                    bl[nt][0] = hs32[rb + 160 + hk + (lane & 3)];
                    bl[nt][1] = hs32[rb + 160 + hk + 4 + (lane & 3)];
                }
#pragma unroll
                for (int i = 0; i < 3; ++i)
#pragma unroll
                    for (int nt = 0; nt < 2; ++nt)
                        MMA_ACC(acc[i][nt], A[i], bh[nt][0], bh[nt][1]);
#pragma unroll
                for (int i = 0; i < 3; ++i)
#pragma unroll
                    for (int nt = 0; nt < 2; ++nt)
                        MMA_ACC(acc[i][nt], A[i], bl[nt][0], bl[nt][1]);
            }
            // ---- lo chunks 19..37: W_lo x h_hi ----
#pragma unroll 1
            for (int kc = 19; kc < RKC; ++kc) {
                const int stage = (kc + sbase) & 3;
                asm volatile("cp.async.wait_group 3;" ::: "memory");
                const uint32_t wbase = swb + (uint32_t)stage * WSTG;
                const int hk = (kc - 19) * 8;
                uint32_t A[3][4];
#pragma unroll
                for (int i = 0; i < 3; ++i) {
                    asm volatile("ldmatrix.sync.aligned.m8n8.x4.shared.b16 "
                                 "{%0,%1,%2,%3}, [%4];"
                                 : "=r"(A[i][0]), "=r"(A[i][1]), "=r"(A[i][2]), "=r"(A[i][3])
                                 : "r"(wbase + afro[i]));
                }
                int pfc = kc + 4; if (pfc >= RKC) pfc -= RKC;
                ISSUE_WCHUNK(pfc, stage);
                uint32_t bh[2][2];
#pragma unroll
                for (int nt = 0; nt < 2; ++nt) {
                    int rb = (nt * 8 + (lane >> 2)) * (HSS / 2);
                    bh[nt][0] = hs32[rb + hk + (lane & 3)];
                    bh[nt][1] = hs32[rb + hk + 4 + (lane & 3)];
                }
#pragma unroll
                for (int i = 0; i < 3; ++i)
#pragma unroll
                    for (int nt = 0; nt < 2; ++nt)
                        MMA_ACC(acc[i][nt], A[i], bh[nt][0], bh[nt][1]);
            }
        } else if (wid == NCW) {
            // ---- producer warp: stream xg(t) for valid graphs into xq ----
            for (int u = lane; u < RBT * 225; u += 32) {
                int b = u / 225, f4 = u - b * 225;
                if (t < sln[b]) {
                    int p = f4 / 75, j4 = f4 - p * 75;
                    const void* src = xg + (size_t)(sst[b] + t) * G + f4 * 4;
                    uint32_t dst = swb + SM_XQ + (uint32_t)(p * XQP + b * 304 + j4 * 4) * 4;
                    asm volatile("cp.async.cg.shared.global [%0], [%1], 16;"
                                 :: "r"(dst), "l"(src));
                }
            }
            asm volatile("cp.async.commit_group;" ::: "memory");
            asm volatile("cp.async.wait_group 0;" ::: "memory");
        }
        __syncthreads();   // xq visible; all MMA h-reads complete

        if (iscomp) {
            // register-resident pointwise GRU update for owned (j, b) pairs
            int j0 = wid * 16 + (lane >> 2);
#pragma unroll
            for (int nt = 0; nt < 2; ++nt) {
                int bb = nt * 8 + (lane & 3) * 2;
#pragma unroll
                for (int e = 0; e < 4; ++e) {
                    int j = j0 + ((e >> 1) << 3);
                    int b = bb + (e & 1);
                    if (j < H) {
                        bool valid = t < sln[b];
                        float x0, x1, x2;
                        if (valid) {
                            x0 = xq[b * 304 + j];
                            x1 = xq[XQP + b * 304 + j];
                            x2 = xq[2 * XQP + b * 304 + j];
                        } else {
                            x0 = sbih[j]; x1 = sbih[H + j]; x2 = sbih[2 * H + j];
                        }
                        float r  = sigm(x0 + acc[0][nt][e] + sbhh[j]);
                        float z  = sigm(x1 + acc[1][nt][e] + sbhh[H + j]);
                        float nn = tanh_fast(x2 + r * (acc[2][nt][e] + sbhh[2 * H + j]));
                        float hp = hf[b * HFS + j];
                        float hv = (1.f - z) * nn + z * hp;
                        hf[b * HFS + j] = hv;
                        __nv_bfloat16 hb = __float2bfloat16(hv);
                        hsb[b * HSS + j] = hb;
                        hsb[b * HSS + 320 + j] = __float2bfloat16(hv - __bfloat162float(hb));
                        if (valid)
                            stcs(out + (size_t)(sst[b] + t) * (2 * H) + dir * H + j, hv);
                    }
                }
            }
        }
        __syncthreads();   // new h visible before next step's MMAs
    }
    if (iscomp) asm volatile("cp.async.wait_group 0;" ::: "memory");
#undef ISSUE_WCHUNK
#undef MMA_ACC
}

// ---------------- host entry ----------------
extern "C" void kernel_launch(void* const* d_in, const int* in_sizes, int n_in,
                              void* d_out, int out_size) {
    const float* node   = (const float*)d_in[0];
    const int*   batch  = (const int*)d_in[1];
    const int*   pos    = (const int*)d_in[2];
    const float* bias   = (const float*)d_in[3];
    const float* w_ih_f = (const float*)d_in[4];
    const float* w_hh_f = (const float*)d_in[5];
    const float* b_ih_f = (const float*)d_in[6];
    const float* b_hh_f = (const float*)d_in[7];
    const float* w_ih_b = (const float*)d_in[8];
    const float* w_hh_b = (const float*)d_in[9];
    const float* b_ih_b = (const float*)d_in[10];
    const float* b_hh_b = (const float*)d_in[11];
    float* out = (float*)d_out;
    int n = in_sizes[0] / H;

    cudaFuncSetAttribute(k_gemm_mma, cudaFuncAttributeMaxDynamicSharedMemorySize, GSM_TOT);
    cudaFuncSetAttribute(k_recur_mma, cudaFuncAttributeMaxDynamicSharedMemorySize, SM_TOT);

    int gprep = 64 + n + 512 + 256;
    k_prep<<<gprep, 256>>>(node, bias, batch, pos, w_ih_f, w_ih_b, w_hh_f, w_hh_b, n);
    k_h0<<<NB, NTHREADS>>>(node);
    k_gemm_mma<<<dim3(16, n / MT), 256, GSM_TOT>>>(b_ih_f, b_ih_b);
    k_recur_mma<<<dim3(NB / RBT, 2), RNT, SM_TOT>>>(b_ih_f, b_ih_b, b_hh_f, b_hh_b, out);
}

// round 15
// speedup vs baseline: 1.8924x; 1.1067x over previous
#include <cuda_runtime.h>
#include <cuda_bf16.h>
#include <math.h>
#include <cstdint>

#define H     300
#define G     900
#define NB    1024
#define LSEQ  64
#define NTHREADS 320
#define NNODES 49152

// ---- input GEMM config ----
#define KP  960
#define NP  1024
#define MT  128
#define NKB2 (KP / 32)
#define SROW 80
#define GSTG 20480
#define GSM_TOT (3 * GSTG)

// ---- recurrent mma config ----
#define GP    304                  // rows per gate (19 m16 tiles)
#define RROWS 912                  // 3*GP, 57 m16 tiles
#define RKC   38                   // 19 hi + 19 lo k16 chunks
#define WSTG  (RROWS * 32)         // ring stage: 29184 B
#define HSS   648                  // h-split row stride (bf16)
#define RBT   16                   // graphs per CTA
#define RNT   608                  // 19 warps, all compute (gate-aligned)
#define NCW   19
#define HSBUF (RBT * HSS * 2)      // 20736 B per h-split buffer

// dynamic smem layout (bytes)
#define SM_W    0
#define SM_HS   (4 * WSTG)                    // 116736: 2 x h-split buffers
#define SM_BH   (SM_HS + 2 * HSBUF)           // 158208
#define SM_BI   (SM_BH + 3600)                // 161808
#define SM_MISC (SM_BI + 3600)                // 165408
#define SM_TOT  (SM_MISC + 128)               // 165536

__device__ __forceinline__ float sigm(float x) { return 1.f / (1.f + __expf(-x)); }
__device__ __forceinline__ float tanh_fast(float x) {
    float s = 1.f / (1.f + __expf(-2.f * x));
    return 2.f * s - 1.f;
}
__device__ __forceinline__ uint32_t smem_u32(const void* p) {
    uint32_t a;
    asm("{ .reg .u64 t; cvta.to.shared.u64 t, %1; cvt.u32.u64 %0, t; }" : "=r"(a) : "l"(p));
    return a;
}
__device__ __forceinline__ float ldcs(const float* p) {
    float v; asm volatile("ld.global.cs.f32 %0, [%1];" : "=f"(v) : "l"(p)); return v;
}
__device__ __forceinline__ void stcs(float* p, float v) {
    asm volatile("st.global.cs.f32 [%0], %1;" :: "l"(p), "f"(v));
}

// ---------------- device scratch ----------------
__device__ __align__(16) __nv_bfloat16 g_abf[(size_t)NNODES * KP];
__device__ __align__(16) __nv_bfloat16 g_bbf[2][(size_t)NP * KP];
__device__ __align__(16) __nv_bfloat16 g_gwr[(size_t)2 * RKC * RROWS * 16];
__device__ float g_xg[2][(size_t)NNODES * G];
__device__ float g_h0[NB * H];
__device__ int   g_sstart[NB];
__device__ int   g_slen[NB];

// ---------------- 1) merged prep: seg | convA | convB | convW ----------------
__global__ void __launch_bounds__(256) k_prep(const float* __restrict__ node,
                                              const float* __restrict__ bias,
                                              const int* __restrict__ batch,
                                              const int* __restrict__ pos,
                                              const float* __restrict__ wif,
                                              const float* __restrict__ wib,
                                              const float* __restrict__ whf,
                                              const float* __restrict__ whb,
                                              int n) {
    __shared__ float sb[H];
    const int bx = blockIdx.x, tid = threadIdx.x;
    if (bx < 64) {
        for (int i = bx * 256 + tid; i < n; i += 64 * 256) {
            int b = batch[i];
            if (pos[i] == 0) g_sstart[b] = i;
            if (i == n - 1 || batch[i + 1] != b) g_slen[b] = pos[i] + 1;
        }
    } else if (bx < 64 + n) {
        int i = bx - 64;
        for (int k = tid; k < H; k += 256) {
            float v = node[(size_t)i * H + k] + bias[k];
            sb[k] = v > 0.f ? v : 0.f;
        }
        __syncthreads();
        __nv_bfloat16* dst = g_abf + (size_t)i * KP;
        for (int kp = tid; kp < KP; kp += 256) {
            __nv_bfloat16 o = __float2bfloat16(0.f);
            int k = -1; bool lo = false;
            if (kp < 300)                    { k = kp; }
            else if (kp >= 320 && kp < 620)  { k = kp - 320; lo = true; }
            else if (kp >= 640 && kp < 940)  { k = kp - 640; }
            if (k >= 0) {
                float m = sb[k];
                __nv_bfloat16 hi = __float2bfloat16(m);
                o = lo ? __float2bfloat16(m - __bfloat162float(hi)) : hi;
            }
            dst[kp] = o;
        }
    } else if (bx < 64 + n + 512) {
        size_t tot = (size_t)2 * NP * KP;
        int bb = bx - 64 - n;
        for (size_t idx = (size_t)bb * 256 + tid; idx < tot; idx += (size_t)512 * 256) {
            int dir = (int)(idx / ((size_t)NP * KP));
            size_t r = idx - (size_t)dir * NP * KP;
            int g = (int)(r / KP), kp = (int)(r - (size_t)g * KP);
            __nv_bfloat16 o = __float2bfloat16(0.f);
            int k = -1; bool lo = false;
            if (kp < 300)                    { k = kp; }
            else if (kp >= 320 && kp < 620)  { k = kp - 320; }
            else if (kp >= 640 && kp < 940)  { k = kp - 640; lo = true; }
            if (k >= 0 && g < G) {
                const float* w = dir ? wib : wif;
                float v = w[(size_t)g * H + k];
                __nv_bfloat16 hi = __float2bfloat16(v);
                o = lo ? __float2bfloat16(v - __bfloat162float(hi)) : hi;
            }
            g_bbf[dir][r] = o;
        }
    } else {
        const int tot = 2 * RKC * RROWS * 16;
        int bb = bx - 64 - n - 512;
        for (int idx = bb * 256 + tid; idx < tot; idx += 256 * 256) {
            int dir = idx / (RKC * RROWS * 16);
            int r = idx % (RKC * RROWS * 16);
            int kc = r / (RROWS * 16);
            int rr = r % (RROWS * 16);
            int row = rr >> 4, c = rr & 15;
            int gate = row / GP, j = row % GP;
            bool lo = kc >= 19;
            int k = (lo ? kc - 19 : kc) * 16 + c;
            __nv_bfloat16 o = __float2bfloat16(0.f);
            if (j < H && k < H) {
                const float* w = dir ? whb : whf;
                float v = w[(size_t)(gate * H + j) * H + k];
                __nv_bfloat16 hi = __float2bfloat16(v);
                o = lo ? __float2bfloat16(v - __bfloat162float(hi)) : hi;
            }
            g_gwr[idx] = o;
        }
    }
}

// ---------------- 2) h0 = per-graph segment max ----------------
__global__ void __launch_bounds__(NTHREADS) k_h0(const float* __restrict__ node) {
    int b = blockIdx.x, h = threadIdx.x;
    if (h >= H) return;
    int s = g_sstart[b], l = g_slen[b];
    float m = -3.402823466e38f;
    for (int i = 0; i < l; ++i) m = fmaxf(m, node[(size_t)(s + i) * H + h]);
    g_h0[b * H + h] = m;
}

// ---------------- 3) input GEMM (proven round-8) ----------------
__global__ void __launch_bounds__(256, 2) k_gemm_mma(const float* __restrict__ bih_f,
                                                     const float* __restrict__ bih_b) {
    extern __shared__ unsigned char gsm[];
    const int tid = threadIdx.x, lane = tid & 31, wid = tid >> 5;
    const int dir = blockIdx.x >> 3, ntile = blockIdx.x & 7;
    const int m0 = blockIdx.y * MT, n0 = ntile * 128;
    const int wm = wid & 3, wn = wid >> 2;

    const __nv_bfloat16* __restrict__ A = g_abf + (size_t)m0 * KP;
    const __nv_bfloat16* __restrict__ B = g_bbf[dir] + (size_t)n0 * KP;
    const uint32_t s0 = smem_u32(gsm);

    float d[2][8][4];
#pragma unroll
    for (int mi = 0; mi < 2; ++mi)
#pragma unroll
        for (int ni = 0; ni < 8; ++ni)
#pragma unroll
            for (int e = 0; e < 4; ++e) d[mi][ni][e] = 0.f;

#define ISSUE_STAGE(kb, stg) do {                                                   \
    _Pragma("unroll")                                                               \
    for (int _p = 0; _p < 2; ++_p) {                                                \
        int _u = _p * 256 + tid, _row = _u >> 2, _c = _u & 3;                       \
        const void* _ga = A + (size_t)_row * KP + (kb) * 32 + _c * 8;               \
        uint32_t _da = s0 + (stg) * GSTG + _row * SROW + _c * 16;                   \
        asm volatile("cp.async.cg.shared.global [%0], [%1], 16;" :: "r"(_da), "l"(_ga)); \
        const void* _gb = B + (size_t)_row * KP + (kb) * 32 + _c * 8;               \
        uint32_t _db = s0 + (stg) * GSTG + 10240 + _row * SROW + _c * 16;           \
        asm volatile("cp.async.cg.shared.global [%0], [%1], 16;" :: "r"(_db), "l"(_gb)); \
    }                                                                               \
    asm volatile("cp.async.commit_group;" ::: "memory");                            \
} while (0)

#define GEMM_COMPUTE(a32, b32, NIMAX)                                               \
    _Pragma("unroll")                                                               \
    for (int ks = 0; ks < 2; ++ks) {                                                \
        uint32_t af[2][4];                                                          \
        _Pragma("unroll")                                                           \
        for (int mi = 0; mi < 2; ++mi) {                                            \
            int r0 = wm * 32 + mi * 16 + (lane >> 2);                               \
            af[mi][0] = (a32)[r0 * 20 + ks * 8 + (lane & 3)];                       \
            af[mi][1] = (a32)[(r0 + 8) * 20 + ks * 8 + (lane & 3)];                 \
            af[mi][2] = (a32)[r0 * 20 + ks * 8 + 4 + (lane & 3)];                   \
            af[mi][3] = (a32)[(r0 + 8) * 20 + ks * 8 + 4 + (lane & 3)];             \
        }                                                                           \
        _Pragma("unroll")                                                           \
        for (int ni = 0; ni < (NIMAX); ++ni) {                                      \
            int cn = wn * 64 + ni * 8 + (lane >> 2);                                \
            uint32_t b0 = (b32)[cn * 20 + ks * 8 + (lane & 3)];                     \
            uint32_t b1 = (b32)[cn * 20 + ks * 8 + 4 + (lane & 3)];                 \
            _Pragma("unroll")                                                       \
            for (int mi = 0; mi < 2; ++mi) {                                        \
                asm volatile(                                                       \
                    "mma.sync.aligned.m16n8k16.row.col.f32.bf16.bf16.f32 "          \
                    "{%0,%1,%2,%3}, {%4,%5,%6,%7}, {%8,%9}, {%0,%1,%2,%3};"         \
                    : "+f"(d[mi][ni][0]), "+f"(d[mi][ni][1]),                       \
                      "+f"(d[mi][ni][2]), "+f"(d[mi][ni][3])                        \
                    : "r"(af[mi][0]), "r"(af[mi][1]), "r"(af[mi][2]), "r"(af[mi][3]), \
                      "r"(b0), "r"(b1));                                            \
            }                                                                       \
        }                                                                           \
    }

    ISSUE_STAGE(0, 0);
    ISSUE_STAGE(1, 1);
    const bool tail = (ntile == 7);
    int stg = 0;
    for (int kb = 0; kb < NKB2; ++kb) {
        if (kb <= NKB2 - 2) { asm volatile("cp.async.wait_group 1;" ::: "memory"); }
        else                { asm volatile("cp.async.wait_group 0;" ::: "memory"); }
        __syncthreads();
        const uint32_t* a32 = (const uint32_t*)(gsm + stg * GSTG);
        const uint32_t* b32 = (const uint32_t*)(gsm + stg * GSTG + 10240);
        if (!tail) { GEMM_COMPUTE(a32, b32, 8); }
        else       { GEMM_COMPUTE(a32, b32, 1); }
        if (kb + 2 < NKB2) {
            int ns = stg + 2; if (ns >= 3) ns -= 3;
            ISSUE_STAGE(kb + 2, ns);
        }
        if (++stg == 3) stg = 0;
    }
#undef ISSUE_STAGE
#undef GEMM_COMPUTE

    const float* __restrict__ bih = dir ? bih_b : bih_f;
    float* __restrict__ xg = g_xg[dir];
    const int nimax = tail ? 1 : 8;
#pragma unroll
    for (int mi = 0; mi < 2; ++mi) {
        int r0 = m0 + wm * 32 + mi * 16 + (lane >> 2);
        for (int ni = 0; ni < nimax; ++ni) {
            int g = n0 + wn * 64 + ni * 8 + (lane & 3) * 2;
            if (g < G) {
                float bg0 = bih[g], bg1 = bih[g + 1];
                *(float2*)(xg + (size_t)r0 * G + g) =
                    make_float2(d[mi][ni][0] + bg0, d[mi][ni][1] + bg1);
                *(float2*)(xg + (size_t)(r0 + 8) * G + g) =
                    make_float2(d[mi][ni][2] + bg0, d[mi][ni][3] + bg1);
            }
        }
    }
}

// ---------------- 4) recurrent GRU: 1 barrier/step, double-buffered h, reg h ----------------
__global__ void __launch_bounds__(RNT, 1) k_recur_mma(const float* __restrict__ bih_f,
                                                      const float* __restrict__ bih_b,
                                                      const float* __restrict__ bhh_f,
                                                      const float* __restrict__ bhh_b,
                                                      float* __restrict__ out) {
    extern __shared__ char smem[];
    float* sbhh = (float*)(smem + SM_BH);
    float* sbih = (float*)(smem + SM_BI);
    int*   sst  = (int*)(smem + SM_MISC);
    int*   sln  = sst + RBT;

    const int tid = threadIdx.x, lane = tid & 31, wid = tid >> 5;
    const int dir = blockIdx.y;
    const int b0 = blockIdx.x * RBT;
    const uint32_t swb = smem_u32(smem);

    // warp w owns tiles {w, w+19, w+38} = gates 0,1,2 of j-group w
    uint32_t afro[3];
    {
        int lsel = lane >> 3, lrow = lane & 7;
        int half = lsel >> 1;
#pragma unroll
        for (int i = 0; i < 3; ++i) {
            int row = (wid + NCW * i) * 16 + lrow + ((lsel & 1) << 3);
            afro[i] = row * 32 + ((half ^ ((row >> 2) & 1)) << 4);
        }
    }

    const __nv_bfloat16* __restrict__ gw = g_gwr + (size_t)dir * RKC * RROWS * 16;
    const float* __restrict__ xg = g_xg[dir];

#define ISSUE_WCHUNK(pfc, stg) do {                                                 \
    const char* _src = (const char*)(gw + (size_t)(pfc) * (RROWS * 16));            \
    _Pragma("unroll")                                                               \
    for (int _i = 0; _i < 3; ++_i) {                                                \
        int _row = (wid + NCW * _i) * 16 + (lane >> 1);                             \
        int _half = lane & 1;                                                       \
        int _hsw = _half ^ ((_row >> 2) & 1);                                       \
        uint32_t _d = swb + (stg) * WSTG + _row * 32 + (_hsw << 4);                 \
        const void* _s = _src + _row * 32 + _half * 16;                             \
        asm volatile("cp.async.cg.shared.global [%0], [%1], 16;" :: "r"(_d), "l"(_s)); \
    }                                                                               \
    asm volatile("cp.async.commit_group;" ::: "memory");                            \
} while (0)

#define MMA_ACC(ac, Af, B0, B1)                                                     \
    asm volatile("mma.sync.aligned.m16n8k16.row.col.f32.bf16.bf16.f32 "             \
        "{%0,%1,%2,%3}, {%4,%5,%6,%7}, {%8,%9}, {%0,%1,%2,%3};"                     \
        : "+f"((ac)[0]), "+f"((ac)[1]), "+f"((ac)[2]), "+f"((ac)[3])                \
        : "r"((Af)[0]), "r"((Af)[1]), "r"((Af)[2]), "r"((Af)[3]), "r"(B0), "r"(B1))

#pragma unroll
    for (int p = 0; p < 4; ++p) ISSUE_WCHUNK(p, p);

    // ---- init: seg info, biases, zero BOTH h-split buffers, write h0 into buf 0 ----
    if (tid < RBT) { sst[tid] = g_sstart[b0 + tid]; sln[tid] = g_slen[b0 + tid]; }
    {
        uint32_t* hz = (uint32_t*)(smem + SM_HS);
        for (int i = tid; i < 2 * RBT * (HSS / 2); i += RNT) hz[i] = 0u;
        const float* bhh = dir ? bhh_b : bhh_f;
        const float* bih = dir ? bih_b : bih_f;
        for (int i = tid; i < G; i += RNT) { sbhh[i] = bhh[i]; sbih[i] = bih[i]; }
    }
    __syncthreads();
    {
        __nv_bfloat16* hsb0 = (__nv_bfloat16*)(smem + SM_HS);
        for (int it = tid; it < RBT * H; it += RNT) {
            int j = it >> 4, b = it & 15;
            float v = g_h0[(b0 + b) * H + j];
            __nv_bfloat16 hb = __float2bfloat16(v);
            hsb0[b * HSS + j] = hb;
            hsb0[b * HSS + 320 + j] = __float2bfloat16(v - __bfloat162float(hb));
        }
    }
    // per-thread fp32 h for owned (j,b)
    const int j0 = wid * 16 + (lane >> 2);
    float hp[2][4];
#pragma unroll
    for (int nt = 0; nt < 2; ++nt)
#pragma unroll
        for (int e = 0; e < 4; ++e) {
            int j = j0 + ((e >> 1) << 3);
            int b = nt * 8 + (lane & 3) * 2 + (e & 1);
            hp[nt][e] = (j < H) ? g_h0[(b0 + b) * H + j] : 0.f;
        }
    __syncthreads();

    for (int s = 0; s < LSEQ; ++s) {
        int t = dir ? (LSEQ - 1 - s) : s;
        const int cur = s & 1, nxt = cur ^ 1;
        const uint32_t* hs32 = (const uint32_t*)(smem + SM_HS + cur * HSBUF);

        // ---- register prefetch of this step's xq for owned (j,b) ----
        float xp[2][4][3];
#pragma unroll
        for (int nt = 0; nt < 2; ++nt)
#pragma unroll
            for (int e = 0; e < 4; ++e) {
                int j = j0 + ((e >> 1) << 3);
                int b = nt * 8 + (lane & 3) * 2 + (e & 1);
                if (j < H) {
                    if (t < sln[b]) {
                        const float* xr = xg + (size_t)(sst[b] + t) * G;
                        xp[nt][e][0] = ldcs(xr + j);
                        xp[nt][e][1] = ldcs(xr + H + j);
                        xp[nt][e][2] = ldcs(xr + 2 * H + j);
                    } else {
                        xp[nt][e][0] = sbih[j];
                        xp[nt][e][1] = sbih[H + j];
                        xp[nt][e][2] = sbih[2 * H + j];
                    }
                }
            }

        float acc[3][2][4];
#pragma unroll
        for (int g = 0; g < 3; ++g)
#pragma unroll
            for (int nt = 0; nt < 2; ++nt)
#pragma unroll
                for (int e = 0; e < 4; ++e) acc[g][nt][e] = 0.f;

        const int sbase = 2 * (s & 1);          // (38*s) mod 4
        // ---- hi chunks 0..18: W_hi x (h_hi + h_lo) ----
#pragma unroll 1
        for (int kc = 0; kc < 19; ++kc) {
            const int stage = (kc + sbase) & 3;
            asm volatile("cp.async.wait_group 3;" ::: "memory");
            const uint32_t wbase = swb + (uint32_t)stage * WSTG;
            const int hk = kc * 8;
            uint32_t A[3][4];
#pragma unroll
            for (int i = 0; i < 3; ++i) {
                asm volatile("ldmatrix.sync.aligned.m8n8.x4.shared.b16 "
                             "{%0,%1,%2,%3}, [%4];"
                             : "=r"(A[i][0]), "=r"(A[i][1]), "=r"(A[i][2]), "=r"(A[i][3])
                             : "r"(wbase + afro[i]));
            }
            int pfc = kc + 4; if (pfc >= RKC) pfc -= RKC;
            ISSUE_WCHUNK(pfc, stage);
            uint32_t bh[2][2], bl[2][2];
#pragma unroll
            for (int nt = 0; nt < 2; ++nt) {
                int rb = (nt * 8 + (lane >> 2)) * (HSS / 2);
                bh[nt][0] = hs32[rb + hk + (lane & 3)];
                bh[nt][1] = hs32[rb + hk + 4 + (lane & 3)];
                bl[nt][0] = hs32[rb + 160 + hk + (lane & 3)];
                bl[nt][1] = hs32[rb + 160 + hk + 4 + (lane & 3)];
            }
#pragma unroll
            for (int i = 0; i < 3; ++i)
#pragma unroll
                for (int nt = 0; nt < 2; ++nt)
                    MMA_ACC(acc[i][nt], A[i], bh[nt][0], bh[nt][1]);
#pragma unroll
            for (int i = 0; i < 3; ++i)
#pragma unroll
                for (int nt = 0; nt < 2; ++nt)
                    MMA_ACC(acc[i][nt], A[i], bl[nt][0], bl[nt][1]);
        }
        // ---- lo chunks 19..37: W_lo x h_hi ----
#pragma unroll 1
        for (int kc = 19; kc < RKC; ++kc) {
            const int stage = (kc + sbase) & 3;
            asm volatile("cp.async.wait_group 3;" ::: "memory");
            const uint32_t wbase = swb + (uint32_t)stage * WSTG;
            const int hk = (kc - 19) * 8;
            uint32_t A[3][4];
#pragma unroll
            for (int i = 0; i < 3; ++i) {
                asm volatile("ldmatrix.sync.aligned.m8n8.x4.shared.b16 "
                             "{%0,%1,%2,%3}, [%4];"
                             : "=r"(A[i][0]), "=r"(A[i][1]), "=r"(A[i][2]), "=r"(A[i][3])
                             : "r"(wbase + afro[i]));
            }
            int pfc = kc + 4; if (pfc >= RKC) pfc -= RKC;
            ISSUE_WCHUNK(pfc, stage);
            uint32_t bh[2][2];
#pragma unroll
            for (int nt = 0; nt < 2; ++nt) {
                int rb = (nt * 8 + (lane >> 2)) * (HSS / 2);
                bh[nt][0] = hs32[rb + hk + (lane & 3)];
                bh[nt][1] = hs32[rb + hk + 4 + (lane & 3)];
            }
#pragma unroll
            for (int i = 0; i < 3; ++i)
#pragma unroll
                for (int nt = 0; nt < 2; ++nt)
                    MMA_ACC(acc[i][nt], A[i], bh[nt][0], bh[nt][1]);
        }

        // ---- pointwise (register acc/xq/h), write new h-split to buffer nxt ----
        __nv_bfloat16* hsbn = (__nv_bfloat16*)(smem + SM_HS + nxt * HSBUF);
#pragma unroll
        for (int nt = 0; nt < 2; ++nt)
#pragma unroll
            for (int e = 0; e < 4; ++e) {
                int j = j0 + ((e >> 1) << 3);
                int b = nt * 8 + (lane & 3) * 2 + (e & 1);
                if (j < H) {
                    float r  = sigm(xp[nt][e][0] + acc[0][nt][e] + sbhh[j]);
                    float z  = sigm(xp[nt][e][1] + acc[1][nt][e] + sbhh[H + j]);
                    float nn = tanh_fast(xp[nt][e][2] + r * (acc[2][nt][e] + sbhh[2 * H + j]));
                    float hv = (1.f - z) * nn + z * hp[nt][e];
                    hp[nt][e] = hv;
                    __nv_bfloat16 hb = __float2bfloat16(hv);
                    hsbn[b * HSS + j] = hb;
                    hsbn[b * HSS + 320 + j] = __float2bfloat16(hv - __bfloat162float(hb));
                    if (t < sln[b])
                        stcs(out + (size_t)(sst[b] + t) * (2 * H) + dir * H + j, hv);
                }
            }
        __syncthreads();   // new h (buffer nxt) visible before next step's MMAs
    }
    asm volatile("cp.async.wait_group 0;" ::: "memory");
#undef ISSUE_WCHUNK
#undef MMA_ACC
}

// ---------------- host entry ----------------
extern "C" void kernel_launch(void* const* d_in, const int* in_sizes, int n_in,
                              void* d_out, int out_size) {
    const float* node   = (const float*)d_in[0];
    const int*   batch  = (const int*)d_in[1];
    const int*   pos    = (const int*)d_in[2];
    const float* bias   = (const float*)d_in[3];
    const float* w_ih_f = (const float*)d_in[4];
    const float* w_hh_f = (const float*)d_in[5];
    const float* b_ih_f = (const float*)d_in[6];
    const float* b_hh_f = (const float*)d_in[7];
    const float* w_ih_b = (const float*)d_in[8];
    const float* w_hh_b = (const float*)d_in[9];
    const float* b_ih_b = (const float*)d_in[10];
    const float* b_hh_b = (const float*)d_in[11];
    float* out = (float*)d_out;
    int n = in_sizes[0] / H;

    cudaFuncSetAttribute(k_gemm_mma, cudaFuncAttributeMaxDynamicSharedMemorySize, GSM_TOT);
    cudaFuncSetAttribute(k_recur_mma, cudaFuncAttributeMaxDynamicSharedMemorySize, SM_TOT);

    int gprep = 64 + n + 512 + 256;
    k_prep<<<gprep, 256>>>(node, bias, batch, pos, w_ih_f, w_ih_b, w_hh_f, w_hh_b, n);
    k_h0<<<NB, NTHREADS>>>(node);
    k_gemm_mma<<<dim3(16, n / MT), 256, GSM_TOT>>>(b_ih_f, b_ih_b);
    k_recur_mma<<<dim3(NB / RBT, 2), RNT, SM_TOT>>>(b_ih_f, b_ih_b, b_hh_f, b_hh_b, out);
}

// round 16
// speedup vs baseline: 1.9002x; 1.0041x over previous
#include <cuda_runtime.h>
#include <cuda_bf16.h>
#include <cuda_fp16.h>
#include <math.h>
#include <cstdint>

#define H     300
#define G     900
#define NB    1024
#define LSEQ  64
#define NTHREADS 320
#define NNODES 49152

// ---- input GEMM config ----
#define KP  960
#define NP  1024
#define MT  128
#define NKB2 (KP / 32)
#define SROW 80
#define GSTG 20480
#define GSM_TOT (3 * GSTG)

// ---- recurrent mma config (fp16 2.5-term) ----
#define GP    304                  // rows per gate (19 m16 tiles)
#define RROWS 912                  // 3*GP, 57 m16 tiles
#define RPR   19                   // k16 chunk-pairs (Whi+Wlo per pair)
#define WSTG  (RROWS * 32)         // ring stage: 29184 B (one W part)
#define HSS   648                  // h-split row stride (fp16)
#define RBT   16                   // graphs per CTA
#define RNT   608                  // 19 warps, gate-aligned
#define NCW   19
#define HSBUF (RBT * HSS * 2)      // 20736 B per h-split buffer
#define CSCL  2048.0f
#define CINV  4.8828125e-4f        // 1/2048

// dynamic smem layout (bytes)
#define SM_W    0
#define SM_HS   (4 * WSTG)                    // 116736: 2 x h-split buffers
#define SM_BH   (SM_HS + 2 * HSBUF)           // 158208
#define SM_BI   (SM_BH + 3600)                // 161808
#define SM_MISC (SM_BI + 3600)                // 165408
#define SM_TOT  (SM_MISC + 128)               // 165536

__device__ __forceinline__ float sigm(float x) { return 1.f / (1.f + __expf(-x)); }
__device__ __forceinline__ float tanh_fast(float x) {
    float s = 1.f / (1.f + __expf(-2.f * x));
    return 2.f * s - 1.f;
}
__device__ __forceinline__ uint32_t smem_u32(const void* p) {
    uint32_t a;
    asm("{ .reg .u64 t; cvta.to.shared.u64 t, %1; cvt.u32.u64 %0, t; }" : "=r"(a) : "l"(p));
    return a;
}
__device__ __forceinline__ float ldcs(const float* p) {
    float v; asm volatile("ld.global.cs.f32 %0, [%1];" : "=f"(v) : "l"(p)); return v;
}
__device__ __forceinline__ void stcs(float* p, float v) {
    asm volatile("st.global.cs.f32 [%0], %1;" :: "l"(p), "f"(v));
}
__device__ __forceinline__ float h16f(uint32_t reg, int hi) {
    unsigned short us = hi ? (unsigned short)(reg >> 16) : (unsigned short)(reg & 0xffff);
    __half h; *(unsigned short*)&h = us;
    return __half2float(h);
}

// ---------------- device scratch ----------------
__device__ __align__(16) __nv_bfloat16 g_abf[(size_t)NNODES * KP];
__device__ __align__(16) __nv_bfloat16 g_bbf[2][(size_t)NP * KP];
// W_hh fp16: [dir][pair 0..18][part 0..1][row 0..911][16]; part1 = Wlo * 2048
__device__ __align__(16) __half g_gwr[(size_t)2 * RPR * 2 * RROWS * 16];
__device__ float g_xg[2][(size_t)NNODES * G];
__device__ float g_h0[NB * H];
__device__ int   g_sstart[NB];
__device__ int   g_slen[NB];

// ---------------- 1) merged prep: seg | convA | convB | convW ----------------
__global__ void __launch_bounds__(256) k_prep(const float* __restrict__ node,
                                              const float* __restrict__ bias,
                                              const int* __restrict__ batch,
                                              const int* __restrict__ pos,
                                              const float* __restrict__ wif,
                                              const float* __restrict__ wib,
                                              const float* __restrict__ whf,
                                              const float* __restrict__ whb,
                                              int n) {
    __shared__ float sb[H];
    const int bx = blockIdx.x, tid = threadIdx.x;
    if (bx < 64) {
        for (int i = bx * 256 + tid; i < n; i += 64 * 256) {
            int b = batch[i];
            if (pos[i] == 0) g_sstart[b] = i;
            if (i == n - 1 || batch[i + 1] != b) g_slen[b] = pos[i] + 1;
        }
    } else if (bx < 64 + n) {
        int i = bx - 64;
        for (int k = tid; k < H; k += 256) {
            float v = node[(size_t)i * H + k] + bias[k];
            sb[k] = v > 0.f ? v : 0.f;
        }
        __syncthreads();
        __nv_bfloat16* dst = g_abf + (size_t)i * KP;
        for (int kp = tid; kp < KP; kp += 256) {
            __nv_bfloat16 o = __float2bfloat16(0.f);
            int k = -1; bool lo = false;
            if (kp < 300)                    { k = kp; }
            else if (kp >= 320 && kp < 620)  { k = kp - 320; lo = true; }
            else if (kp >= 640 && kp < 940)  { k = kp - 640; }
            if (k >= 0) {
                float m = sb[k];
                __nv_bfloat16 hi = __float2bfloat16(m);
                o = lo ? __float2bfloat16(m - __bfloat162float(hi)) : hi;
            }
            dst[kp] = o;
        }
    } else if (bx < 64 + n + 512) {
        size_t tot = (size_t)2 * NP * KP;
        int bb = bx - 64 - n;
        for (size_t idx = (size_t)bb * 256 + tid; idx < tot; idx += (size_t)512 * 256) {
            int dir = (int)(idx / ((size_t)NP * KP));
            size_t r = idx - (size_t)dir * NP * KP;
            int g = (int)(r / KP), kp = (int)(r - (size_t)g * KP);
            __nv_bfloat16 o = __float2bfloat16(0.f);
            int k = -1; bool lo = false;
            if (kp < 300)                    { k = kp; }
            else if (kp >= 320 && kp < 620)  { k = kp - 320; }
            else if (kp >= 640 && kp < 940)  { k = kp - 640; lo = true; }
            if (k >= 0 && g < G) {
                const float* w = dir ? wib : wif;
                float v = w[(size_t)g * H + k];
                __nv_bfloat16 hi = __float2bfloat16(v);
                o = lo ? __float2bfloat16(v - __bfloat162float(hi)) : hi;
            }
            g_bbf[dir][r] = o;
        }
    } else {
        // ---- convW: fp16 split, pair layout [dir][pr][part][row][16] ----
        const int tot = 2 * RPR * 2 * RROWS * 16;
        int bb = bx - 64 - n - 512;
        for (int idx = bb * 256 + tid; idx < tot; idx += 256 * 256) {
            int c = idx & 15;
            int r1 = idx >> 4;
            int row = r1 % RROWS;
            int r2 = r1 / RROWS;
            int part = r2 & 1;
            int r3 = r2 >> 1;
            int pr = r3 % RPR;
            int dir = r3 / RPR;
            int gate = row / GP, j = row % GP;
            int k = pr * 16 + c;
            __half o = __float2half(0.f);
            if (j < H && k < H) {
                const float* w = dir ? whb : whf;
                float v = w[(size_t)(gate * H + j) * H + k];
                __half hi = __float2half(v);
                o = part ? __float2half((v - __half2float(hi)) * CSCL) : hi;
            }
            g_gwr[idx] = o;
        }
    }
}

// ---------------- 2) h0 = per-graph segment max ----------------
__global__ void __launch_bounds__(NTHREADS) k_h0(const float* __restrict__ node) {
    int b = blockIdx.x, h = threadIdx.x;
    if (h >= H) return;
    int s = g_sstart[b], l = g_slen[b];
    float m = -3.402823466e38f;
    for (int i = 0; i < l; ++i) m = fmaxf(m, node[(size_t)(s + i) * H + h]);
    g_h0[b * H + h] = m;
}

// ---------------- 3) input GEMM (proven round-8) ----------------
__global__ void __launch_bounds__(256, 2) k_gemm_mma(const float* __restrict__ bih_f,
                                                     const float* __restrict__ bih_b) {
    extern __shared__ unsigned char gsm[];
    const int tid = threadIdx.x, lane = tid & 31, wid = tid >> 5;
    const int dir = blockIdx.x >> 3, ntile = blockIdx.x & 7;
    const int m0 = blockIdx.y * MT, n0 = ntile * 128;
    const int wm = wid & 3, wn = wid >> 2;

    const __nv_bfloat16* __restrict__ A = g_abf + (size_t)m0 * KP;
    const __nv_bfloat16* __restrict__ B = g_bbf[dir] + (size_t)n0 * KP;
    const uint32_t s0 = smem_u32(gsm);

    float d[2][8][4];
#pragma unroll
    for (int mi = 0; mi < 2; ++mi)
#pragma unroll
        for (int ni = 0; ni < 8; ++ni)
#pragma unroll
            for (int e = 0; e < 4; ++e) d[mi][ni][e] = 0.f;

#define ISSUE_STAGE(kb, stg) do {                                                   \
    _Pragma("unroll")                                                               \
    for (int _p = 0; _p < 2; ++_p) {                                                \
        int _u = _p * 256 + tid, _row = _u >> 2, _c = _u & 3;                       \
        const void* _ga = A + (size_t)_row * KP + (kb) * 32 + _c * 8;               \
        uint32_t _da = s0 + (stg) * GSTG + _row * SROW + _c * 16;                   \
        asm volatile("cp.async.cg.shared.global [%0], [%1], 16;" :: "r"(_da), "l"(_ga)); \
        const void* _gb = B + (size_t)_row * KP + (kb) * 32 + _c * 8;               \
        uint32_t _db = s0 + (stg) * GSTG + 10240 + _row * SROW + _c * 16;           \
        asm volatile("cp.async.cg.shared.global [%0], [%1], 16;" :: "r"(_db), "l"(_gb)); \
    }                                                                               \
    asm volatile("cp.async.commit_group;" ::: "memory");                            \
} while (0)

#define GEMM_COMPUTE(a32, b32, NIMAX)                                               \
    _Pragma("unroll")                                                               \
    for (int ks = 0; ks < 2; ++ks) {                                                \
        uint32_t af[2][4];                                                          \
        _Pragma("unroll")                                                           \
        for (int mi = 0; mi < 2; ++mi) {                                            \
            int r0 = wm * 32 + mi * 16 + (lane >> 2);                               \
            af[mi][0] = (a32)[r0 * 20 + ks * 8 + (lane & 3)];                       \
            af[mi][1] = (a32)[(r0 + 8) * 20 + ks * 8 + (lane & 3)];                 \
            af[mi][2] = (a32)[r0 * 20 + ks * 8 + 4 + (lane & 3)];                   \
            af[mi][3] = (a32)[(r0 + 8) * 20 + ks * 8 + 4 + (lane & 3)];             \
        }                                                                           \
        _Pragma("unroll")                                                           \
        for (int ni = 0; ni < (NIMAX); ++ni) {                                      \
            int cn = wn * 64 + ni * 8 + (lane >> 2);                                \
            uint32_t b0 = (b32)[cn * 20 + ks * 8 + (lane & 3)];                     \
            uint32_t b1 = (b32)[cn * 20 + ks * 8 + 4 + (lane & 3)];                 \
            _Pragma("unroll")                                                       \
            for (int mi = 0; mi < 2; ++mi) {                                        \
                asm volatile(                                                       \
                    "mma.sync.aligned.m16n8k16.row.col.f32.bf16.bf16.f32 "          \
                    "{%0,%1,%2,%3}, {%4,%5,%6,%7}, {%8,%9}, {%0,%1,%2,%3};"         \
                    : "+f"(d[mi][ni][0]), "+f"(d[mi][ni][1]),                       \
                      "+f"(d[mi][ni][2]), "+f"(d[mi][ni][3])                        \
                    : "r"(af[mi][0]), "r"(af[mi][1]), "r"(af[mi][2]), "r"(af[mi][3]), \
                      "r"(b0), "r"(b1));                                            \
            }                                                                       \
        }                                                                           \
    }

    ISSUE_STAGE(0, 0);
    ISSUE_STAGE(1, 1);
    const bool tail = (ntile == 7);
    int stg = 0;
    for (int kb = 0; kb < NKB2; ++kb) {
        if (kb <= NKB2 - 2) { asm volatile("cp.async.wait_group 1;" ::: "memory"); }
        else                { asm volatile("cp.async.wait_group 0;" ::: "memory"); }
        __syncthreads();
        const uint32_t* a32 = (const uint32_t*)(gsm + stg * GSTG);
        const uint32_t* b32 = (const uint32_t*)(gsm + stg * GSTG + 10240);
        if (!tail) { GEMM_COMPUTE(a32, b32, 8); }
        else       { GEMM_COMPUTE(a32, b32, 1); }
        if (kb + 2 < NKB2) {
            int ns = stg + 2; if (ns >= 3) ns -= 3;
            ISSUE_STAGE(kb + 2, ns);
        }
        if (++stg == 3) stg = 0;
    }
#undef ISSUE_STAGE
#undef GEMM_COMPUTE

    const float* __restrict__ bih = dir ? bih_b : bih_f;
    float* __restrict__ xg = g_xg[dir];
    const int nimax = tail ? 1 : 8;
#pragma unroll
    for (int mi = 0; mi < 2; ++mi) {
        int r0 = m0 + wm * 32 + mi * 16 + (lane >> 2);
        for (int ni = 0; ni < nimax; ++ni) {
            int g = n0 + wn * 64 + ni * 8 + (lane & 3) * 2;
            if (g < G) {
                float bg0 = bih[g], bg1 = bih[g + 1];
                *(float2*)(xg + (size_t)r0 * G + g) =
                    make_float2(d[mi][ni][0] + bg0, d[mi][ni][1] + bg1);
                *(float2*)(xg + (size_t)(r0 + 8) * G + g) =
                    make_float2(d[mi][ni][2] + bg0, d[mi][ni][3] + bg1);
            }
        }
    }
}

// ---------------- 4) recurrent GRU: fp16 main + scaled fp16-accum corrections ----------------
__global__ void __launch_bounds__(RNT, 1) k_recur_mma(const float* __restrict__ bih_f,
                                                      const float* __restrict__ bih_b,
                                                      const float* __restrict__ bhh_f,
                                                      const float* __restrict__ bhh_b,
                                                      float* __restrict__ out) {
    extern __shared__ char smem[];
    float* sbhh = (float*)(smem + SM_BH);
    float* sbih = (float*)(smem + SM_BI);
    int*   sst  = (int*)(smem + SM_MISC);
    int*   sln  = sst + RBT;

    const int tid = threadIdx.x, lane = tid & 31, wid = tid >> 5;
    const int dir = blockIdx.y;
    const int b0 = blockIdx.x * RBT;
    const uint32_t swb = smem_u32(smem);

    uint32_t afro[3];
    {
        int lsel = lane >> 3, lrow = lane & 7;
        int half = lsel >> 1;
#pragma unroll
        for (int i = 0; i < 3; ++i) {
            int row = (wid + NCW * i) * 16 + lrow + ((lsel & 1) << 3);
            afro[i] = row * 32 + ((half ^ ((row >> 2) & 1)) << 4);
        }
    }

    const __half* __restrict__ gw = g_gwr + (size_t)dir * RPR * 2 * RROWS * 16;
    const float* __restrict__ xg = g_xg[dir];

// issue one pair (Whi -> stage sA, Wlo -> stage sB); single commit group
#define ISSUE_PAIR(pfc, sA, sB) do {                                                \
    const char* _s0 = (const char*)(gw + ((size_t)(pfc) * 2)     * (RROWS * 16));   \
    const char* _s1 = (const char*)(gw + ((size_t)(pfc) * 2 + 1) * (RROWS * 16));   \
    _Pragma("unroll")                                                               \
    for (int _i = 0; _i < 3; ++_i) {                                                \
        int _row = (wid + NCW * _i) * 16 + (lane >> 1);                             \
        int _half = lane & 1;                                                       \
        int _hsw = _half ^ ((_row >> 2) & 1);                                       \
        uint32_t _off = _row * 32 + (_hsw << 4);                                    \
        uint32_t _go  = _row * 32 + _half * 16;                                     \
        asm volatile("cp.async.cg.shared.global [%0], [%1], 16;"                    \
                     :: "r"(swb + (sA) * WSTG + _off), "l"(_s0 + _go));             \
        asm volatile("cp.async.cg.shared.global [%0], [%1], 16;"                    \
                     :: "r"(swb + (sB) * WSTG + _off), "l"(_s1 + _go));             \
    }                                                                               \
    asm volatile("cp.async.commit_group;" ::: "memory");                            \
} while (0)

#define LDM_A(dst, stg) do {                                                        \
    uint32_t _wb = swb + (uint32_t)(stg) * WSTG;                                    \
    _Pragma("unroll")                                                               \
    for (int _i = 0; _i < 3; ++_i) {                                                \
        asm volatile("ldmatrix.sync.aligned.m8n8.x4.shared.b16 "                    \
                     "{%0,%1,%2,%3}, [%4];"                                         \
                     : "=r"((dst)[_i][0]), "=r"((dst)[_i][1]),                      \
                       "=r"((dst)[_i][2]), "=r"((dst)[_i][3])                       \
                     : "r"(_wb + afro[_i]));                                        \
    }                                                                               \
} while (0)

#define MMA_F32(ac, Af, B0, B1)                                                     \
    asm volatile("mma.sync.aligned.m16n8k16.row.col.f32.f16.f16.f32 "               \
        "{%0,%1,%2,%3}, {%4,%5,%6,%7}, {%8,%9}, {%0,%1,%2,%3};"                     \
        : "+f"((ac)[0]), "+f"((ac)[1]), "+f"((ac)[2]), "+f"((ac)[3])                \
        : "r"((Af)[0]), "r"((Af)[1]), "r"((Af)[2]), "r"((Af)[3]), "r"(B0), "r"(B1))

#define MMA_F16(cc, Af, B0, B1)                                                     \
    asm volatile("mma.sync.aligned.m16n8k16.row.col.f16.f16.f16.f16 "               \
        "{%0,%1}, {%2,%3,%4,%5}, {%6,%7}, {%0,%1};"                                 \
        : "+r"((cc)[0]), "+r"((cc)[1])                                              \
        : "r"((Af)[0]), "r"((Af)[1]), "r"((Af)[2]), "r"((Af)[3]), "r"(B0), "r"(B1))

    ISSUE_PAIR(0, 0, 1);
    ISSUE_PAIR(1, 2, 3);

    // ---- init ----
    if (tid < RBT) { sst[tid] = g_sstart[b0 + tid]; sln[tid] = g_slen[b0 + tid]; }
    {
        uint32_t* hz = (uint32_t*)(smem + SM_HS);
        for (int i = tid; i < 2 * RBT * (HSS / 2); i += RNT) hz[i] = 0u;
        const float* bhh = dir ? bhh_b : bhh_f;
        const float* bih = dir ? bih_b : bih_f;
        for (int i = tid; i < G; i += RNT) { sbhh[i] = bhh[i]; sbih[i] = bih[i]; }
    }
    __syncthreads();
    {
        __half* hs0 = (__half*)(smem + SM_HS);
        for (int it = tid; it < RBT * H; it += RNT) {
            int j = it >> 4, b = it & 15;
            float v = g_h0[(b0 + b) * H + j];
            __half hh = __float2half(v);
            hs0[b * HSS + j] = hh;
            hs0[b * HSS + 320 + j] = __float2half((v - __half2float(hh)) * CSCL);
        }
    }
    const int j0 = wid * 16 + (lane >> 2);
    float hp[2][4];
#pragma unroll
    for (int nt = 0; nt < 2; ++nt)
#pragma unroll
        for (int e = 0; e < 4; ++e) {
            int j = j0 + ((e >> 1) << 3);
            int b = nt * 8 + (lane & 3) * 2 + (e & 1);
            hp[nt][e] = (j < H) ? g_h0[(b0 + b) * H + j] : 0.f;
        }
    __syncthreads();

    for (int s = 0; s < LSEQ; ++s) {
        int t = dir ? (LSEQ - 1 - s) : s;
        const int cur = s & 1, nxt = cur ^ 1;
        const uint32_t* hs32 = (const uint32_t*)(smem + SM_HS + cur * HSBUF);

        float acc[3][2][4];
        uint32_t cf[3][2][2];
#pragma unroll
        for (int g = 0; g < 3; ++g)
#pragma unroll
            for (int nt = 0; nt < 2; ++nt) {
#pragma unroll
                for (int e = 0; e < 4; ++e) acc[g][nt][e] = 0.f;
                cf[g][nt][0] = 0u; cf[g][nt][1] = 0u;
            }

#pragma unroll 1
        for (int kc = 0; kc < RPR; ++kc) {
            const int sA = (2 * (s + kc)) & 3, sB = sA + 1;
            asm volatile("cp.async.wait_group 1;" ::: "memory");   // pair kc landed
            const int hk = kc * 8;
            uint32_t Ahi[3][4];
            LDM_A(Ahi, sA);
            uint32_t bh[2][2];
#pragma unroll
            for (int nt = 0; nt < 2; ++nt) {
                int rb = (nt * 8 + (lane >> 2)) * (HSS / 2);
                bh[nt][0] = hs32[rb + hk + (lane & 3)];
                bh[nt][1] = hs32[rb + hk + 4 + (lane & 3)];
            }
            // main: Whi . hhi (fp32 accum)
#pragma unroll
            for (int i = 0; i < 3; ++i)
#pragma unroll
                for (int nt = 0; nt < 2; ++nt)
                    MMA_F32(acc[i][nt], Ahi[i], bh[nt][0], bh[nt][1]);
            // corr2: Whi . hlo_s (fp16 accum)
            uint32_t bl[2][2];
#pragma unroll
            for (int nt = 0; nt < 2; ++nt) {
                int rb = (nt * 8 + (lane >> 2)) * (HSS / 2);
                bl[nt][0] = hs32[rb + 160 + hk + (lane & 3)];
                bl[nt][1] = hs32[rb + 160 + hk + 4 + (lane & 3)];
            }
#pragma unroll
            for (int i = 0; i < 3; ++i)
#pragma unroll
                for (int nt = 0; nt < 2; ++nt)
                    MMA_F16(cf[i][nt], Ahi[i], bl[nt][0], bl[nt][1]);
            // corr1: Wlo_s . hhi (fp16 accum)
            uint32_t Alo[3][4];
            LDM_A(Alo, sB);
            int pfc = kc + 2; if (pfc >= RPR) pfc -= RPR;
            ISSUE_PAIR(pfc, sA, sB);
#pragma unroll
            for (int i = 0; i < 3; ++i)
#pragma unroll
                for (int nt = 0; nt < 2; ++nt)
                    MMA_F16(cf[i][nt], Alo[i], bh[nt][0], bh[nt][1]);
        }

        // ---- pointwise in registers; new h-split to buffer nxt ----
        __half* hsbn = (__half*)(smem + SM_HS + nxt * HSBUF);
#pragma unroll
        for (int nt = 0; nt < 2; ++nt)
#pragma unroll
            for (int e = 0; e < 4; ++e) {
                int j = j0 + ((e >> 1) << 3);
                int b = nt * 8 + (lane & 3) * 2 + (e & 1);
                if (j < H) {
                    bool valid = t < sln[b];
                    float x0, x1, x2;
                    if (valid) {
                        const float* xr = xg + (size_t)(sst[b] + t) * G;
                        x0 = ldcs(xr + j); x1 = ldcs(xr + H + j); x2 = ldcs(xr + 2 * H + j);
                    } else {
                        x0 = sbih[j]; x1 = sbih[H + j]; x2 = sbih[2 * H + j];
                    }
                    float c0 = h16f(cf[0][nt][e >> 1], e & 1) * CINV;
                    float c1 = h16f(cf[1][nt][e >> 1], e & 1) * CINV;
                    float c2 = h16f(cf[2][nt][e >> 1], e & 1) * CINV;
                    float r  = sigm(x0 + acc[0][nt][e] + c0 + sbhh[j]);
                    float z  = sigm(x1 + acc[1][nt][e] + c1 + sbhh[H + j]);
                    float nn = tanh_fast(x2 + r * (acc[2][nt][e] + c2 + sbhh[2 * H + j]));
                    float hv = (1.f - z) * nn + z * hp[nt][e];
                    hp[nt][e] = hv;
                    __half hh = __float2half(hv);
                    hsbn[b * HSS + j] = hh;
                    hsbn[b * HSS + 320 + j] = __float2half((hv - __half2float(hh)) * CSCL);
                    if (valid)
                        stcs(out + (size_t)(sst[b] + t) * (2 * H) + dir * H + j, hv);
                }
            }
        __syncthreads();   // new h (buffer nxt) visible before next step's MMAs
    }
    asm volatile("cp.async.wait_group 0;" ::: "memory");
#undef ISSUE_PAIR
#undef LDM_A
#undef MMA_F32
#undef MMA_F16
}

// ---------------- host entry ----------------
extern "C" void kernel_launch(void* const* d_in, const int* in_sizes, int n_in,
                              void* d_out, int out_size) {
    const float* node   = (const float*)d_in[0];
    const int*   batch  = (const int*)d_in[1];
    const int*   pos    = (const int*)d_in[2];
    const float* bias   = (const float*)d_in[3];
    const float* w_ih_f = (const float*)d_in[4];
    const float* w_hh_f = (const float*)d_in[5];
    const float* b_ih_f = (const float*)d_in[6];
    const float* b_hh_f = (const float*)d_in[7];
    const float* w_ih_b = (const float*)d_in[8];
    const float* w_hh_b = (const float*)d_in[9];
    const float* b_ih_b = (const float*)d_in[10];
    const float* b_hh_b = (const float*)d_in[11];
    float* out = (float*)d_out;
    int n = in_sizes[0] / H;

    cudaFuncSetAttribute(k_gemm_mma, cudaFuncAttributeMaxDynamicSharedMemorySize, GSM_TOT);
    cudaFuncSetAttribute(k_recur_mma, cudaFuncAttributeMaxDynamicSharedMemorySize, SM_TOT);

    int gprep = 64 + n + 512 + 256;
    k_prep<<<gprep, 256>>>(node, bias, batch, pos, w_ih_f, w_ih_b, w_hh_f, w_hh_b, n);
    k_h0<<<NB, NTHREADS>>>(node);
    k_gemm_mma<<<dim3(16, n / MT), 256, GSM_TOT>>>(b_ih_f, b_ih_b);
    k_recur_mma<<<dim3(NB / RBT, 2), RNT, SM_TOT>>>(b_ih_f, b_ih_b, b_hh_f, b_hh_b, out);
}